// round 4
// baseline (speedup 1.0000x reference)
#include <cuda_runtime.h>
#include <math.h>
#include <stdint.h>

// ---- problem constants ----
#define CB   128
#define CNA  32
#define CN   4096      // atoms
#define CE   65536     // edges
#define CT   262144    // triplets
#define CNR  64
#define CNS  16
#define CEA  128
#define CEE  128
#define CDT  64
#define CLAT 128
#define CHID 256
#define CNC  230

// ---- scratch (device globals: no allocation allowed) ----
__device__ float g_pos[CN*3];
__device__ float g_vec[CE*3];
__device__ float g_rbf[CE*CNR];
__device__ float g_cbf[CT*CNS];
__device__ float g_h [CN*CEA];
__device__ float g_hs[CN*CEA];
__device__ float g_ht[CN*CEA];
__device__ float g_a [CN*CEA];
__device__ float g_m [CE*CEE];
__device__ float g_P [CE*CEE];
__device__ float g_R [CE*CEE];
__device__ float g_X [CE*CDT];
__device__ float g_S [CE*CDT];
__device__ float g_z [CB*CLAT];
__device__ float g_x1[CB*CHID];
__device__ float g_x2[CB*CHID];

__device__ __forceinline__ float siluf(float x) { return x / (1.0f + expf(-x)); }

__device__ __forceinline__ uint32_t f2tf32(float x) {
    uint32_t r;
    asm("cvt.rna.tf32.f32 %0, %1;" : "=r"(r) : "f"(x));
    return r;
}

__device__ __forceinline__ void mma_tf32(float c[4], const uint32_t a[4], const uint32_t b[2]) {
    asm volatile(
        "mma.sync.aligned.m16n8k8.row.col.f32.tf32.tf32.f32 "
        "{%0,%1,%2,%3}, {%4,%5,%6,%7}, {%8,%9}, {%0,%1,%2,%3};"
        : "+f"(c[0]), "+f"(c[1]), "+f"(c[2]), "+f"(c[3])
        : "r"(a[0]), "r"(a[1]), "r"(a[2]), "r"(a[3]), "r"(b[0]), "r"(b[1]));
}

// ============================================================
// TF32 tensor-core GEMM: C[M,N] = epi(A[M,K] @ Bw[K,N])
// CTA tile 128x64, 4 warps (2x2), warp tile 64x32, BK=16,
// double-buffered smem, XOR-swizzled A tile.
// Requires: M%128==0, N%64==0, K%16==0 (true for all calls here).
// EPI 0: C = acc
// EPI 1: C = silu(acc) * D
// EPI 2: C += silu(acc)
// ============================================================
template<int EPI>
__global__ void __launch_bounds__(128)
gemm_tf32(const float* __restrict__ A, const float* __restrict__ Bw,
          const float* __restrict__ D, float* __restrict__ C,
          int M, int N, int K)
{
    __shared__ uint32_t As[2][16][136];  // [buf][k][m swizzled], stride 136 -> bank = 8k+m
    __shared__ uint32_t Bs[2][16][72];   // [buf][k][n], stride 72 -> bank = 8k+n

    const int tid  = threadIdx.x;
    const int lane = tid & 31;
    const int wid  = tid >> 5;
    const int wm   = (wid & 1) * 64;
    const int wn   = (wid >> 1) * 32;
    const int m0   = blockIdx.y * 128;
    const int n0   = blockIdx.x * 64;
    const int nk   = K >> 4;

    // A-load geometry: thread owns row (tid>>2)+32q, float4 at f4*4 within BK
    const int arow = tid >> 2;
    const int af4  = tid & 3;
    // B-load geometry: thread owns k=(tid>>4)+8r, 4 floats at (tid&15)*4
    const int bk   = tid >> 4;
    const int bn4  = (tid & 15) << 2;

    float4 areg[4];
    float4 breg[2];

    auto gload = [&](int k0) {
        #pragma unroll
        for (int q = 0; q < 4; q++) {
            int m = q * 32 + arow;
            areg[q] = *reinterpret_cast<const float4*>(A + (size_t)(m0 + m) * K + k0 + af4 * 4);
        }
        #pragma unroll
        for (int r = 0; r < 2; r++) {
            int k = bk + r * 8;
            breg[r] = *reinterpret_cast<const float4*>(Bw + (size_t)(k0 + k) * N + n0 + bn4);
        }
    };

    auto ssave = [&](int buf) {
        // A: k rows af4*4..af4*4+3, logical col m, physical col m ^ (af4<<3)
        #pragma unroll
        for (int q = 0; q < 4; q++) {
            int m  = q * 32 + arow;
            int mc = m ^ (af4 << 3);
            As[buf][af4 * 4 + 0][mc] = f2tf32(areg[q].x);
            As[buf][af4 * 4 + 1][mc] = f2tf32(areg[q].y);
            As[buf][af4 * 4 + 2][mc] = f2tf32(areg[q].z);
            As[buf][af4 * 4 + 3][mc] = f2tf32(areg[q].w);
        }
        #pragma unroll
        for (int r = 0; r < 2; r++) {
            int k = bk + r * 8;
            uint4 v;
            v.x = f2tf32(breg[r].x); v.y = f2tf32(breg[r].y);
            v.z = f2tf32(breg[r].z); v.w = f2tf32(breg[r].w);
            *reinterpret_cast<uint4*>(&Bs[buf][k][bn4]) = v;
        }
    };

    float acc[4][4][4] = {};

    gload(0);
    ssave(0);
    __syncthreads();

    for (int kb = 0; kb < nk; kb++) {
        int cur = kb & 1;
        if (kb + 1 < nk) gload((kb + 1) << 4);

        #pragma unroll
        for (int kt = 0; kt < 2; kt++) {
            uint32_t af[4][4], bf[4][2];
            int kr  = kt * 8 + (lane & 3);
            int sw0 = ((kr >> 2) & 3) << 3;
            int sw1 = (((kr + 4) >> 2) & 3) << 3;
            #pragma unroll
            for (int mt = 0; mt < 4; mt++) {
                int m = wm + mt * 16 + (lane >> 2);
                af[mt][0] = As[cur][kr    ][m       ^ sw0];
                af[mt][1] = As[cur][kr    ][(m + 8) ^ sw0];
                af[mt][2] = As[cur][kr + 4][m       ^ sw1];
                af[mt][3] = As[cur][kr + 4][(m + 8) ^ sw1];
            }
            #pragma unroll
            for (int nt = 0; nt < 4; nt++) {
                int n = wn + nt * 8 + (lane >> 2);
                bf[nt][0] = Bs[cur][kr    ][n];
                bf[nt][1] = Bs[cur][kr + 4][n];
            }
            #pragma unroll
            for (int mt = 0; mt < 4; mt++)
                #pragma unroll
                for (int nt = 0; nt < 4; nt++)
                    mma_tf32(acc[mt][nt], af[mt], bf[nt]);
        }

        if (kb + 1 < nk) ssave(cur ^ 1);
        __syncthreads();
    }

    // Epilogue
    #pragma unroll
    for (int mt = 0; mt < 4; mt++) {
        #pragma unroll
        for (int nt = 0; nt < 4; nt++) {
            int row = m0 + wm + mt * 16 + (lane >> 2);
            int col = n0 + wn + nt * 8 + ((lane & 3) << 1);
            size_t i0 = (size_t)row * N + col;
            size_t i1 = (size_t)(row + 8) * N + col;
            float2 v0 = make_float2(acc[mt][nt][0], acc[mt][nt][1]);
            float2 v1 = make_float2(acc[mt][nt][2], acc[mt][nt][3]);
            if (EPI == 0) {
                *reinterpret_cast<float2*>(C + i0) = v0;
                *reinterpret_cast<float2*>(C + i1) = v1;
            } else if (EPI == 1) {
                float2 d0 = *reinterpret_cast<const float2*>(D + i0);
                float2 d1 = *reinterpret_cast<const float2*>(D + i1);
                v0.x = siluf(v0.x) * d0.x; v0.y = siluf(v0.y) * d0.y;
                v1.x = siluf(v1.x) * d1.x; v1.y = siluf(v1.y) * d1.y;
                *reinterpret_cast<float2*>(C + i0) = v0;
                *reinterpret_cast<float2*>(C + i1) = v1;
            } else {
                float2 c0 = *reinterpret_cast<const float2*>(C + i0);
                float2 c1 = *reinterpret_cast<const float2*>(C + i1);
                c0.x += siluf(v0.x); c0.y += siluf(v0.y);
                c1.x += siluf(v1.x); c1.y += siluf(v1.y);
                *reinterpret_cast<float2*>(C + i0) = c0;
                *reinterpret_cast<float2*>(C + i1) = c1;
            }
        }
    }
}

__global__ void zero_k(float* __restrict__ p, int n)
{
    int i = blockIdx.x * blockDim.x + threadIdx.x;
    if (i < n) p[i] = 0.0f;
}

// ---- geometry ----
__global__ void pos_kernel(const float* __restrict__ frac, const float* __restrict__ len,
                           const float* __restrict__ ang)
{
    int n = blockIdx.x * blockDim.x + threadIdx.x;
    if (n >= CN) return;
    int b = n >> 5;
    const float D2R = 0.017453292519943295f;
    float La = len[b*3+0], Lb = len[b*3+1], Lc = len[b*3+2];
    float al = ang[b*3+0]*D2R, be = ang[b*3+1]*D2R, ga = ang[b*3+2]*D2R;
    float ca = cosf(al), cb = cosf(be), cg = cosf(ga), sg = sinf(ga);
    float v1x = La;
    float v2x = Lb * cg, v2y = Lb * sg;
    float cx = cb;
    float cy = (ca - cb * cg) / sg;
    float cz = sqrtf(fmaxf(1.0f - cx*cx - cy*cy, 1e-8f));
    float v3x = Lc * cx, v3y = Lc * cy, v3z = Lc * cz;
    float f0 = frac[n*3+0], f1 = frac[n*3+1], f2 = frac[n*3+2];
    g_pos[n*3+0] = f0*v1x + f1*v2x + f2*v3x;
    g_pos[n*3+1] = f1*v2y + f2*v3y;
    g_pos[n*3+2] = f2*v3z;
}

__global__ void vec_kernel(const int* __restrict__ ei)
{
    int e = blockIdx.x * blockDim.x + threadIdx.x;
    if (e >= CE) return;
    int s = ei[e], d = ei[CE + e];
    g_vec[e*3+0] = g_pos[d*3+0] - g_pos[s*3+0];
    g_vec[e*3+1] = g_pos[d*3+1] - g_pos[s*3+1];
    g_vec[e*3+2] = g_pos[d*3+2] - g_pos[s*3+2];
}

__global__ void rbf_kernel()
{
    int idx = blockIdx.x * blockDim.x + threadIdx.x;  // < CE*64
    int e = idx >> 6, r = idx & 63;
    float vx = g_vec[e*3+0], vy = g_vec[e*3+1], vz = g_vec[e*3+2];
    float d = sqrtf(vx*vx + vy*vy + vz*vz + 1e-12f);
    float ds = d * (1.0f / 7.0f);
    float env = 0.0f;
    if (ds < 1.0f) {
        float ds2 = ds*ds, ds4 = ds2*ds2, ds5 = ds4*ds;
        float ds6 = ds5*ds, ds7 = ds6*ds;
        env = 1.0f - 21.0f*ds5 + 35.0f*ds6 - 15.0f*ds7;
    }
    float nn = (float)(r + 1);
    g_rbf[idx] = env * 0.5345224838248488f * sinf(nn * 3.14159265358979323846f * ds) / d;
}

__global__ void cbf_kernel(const int* __restrict__ ji, const int* __restrict__ kj)
{
    int t = blockIdx.x * blockDim.x + threadIdx.x;
    if (t >= CT) return;
    int a = ji[t], b2 = kj[t];
    float ax = g_vec[a*3+0], ay = g_vec[a*3+1], az = g_vec[a*3+2];
    float bx = g_vec[b2*3+0], by = g_vec[b2*3+1], bz = g_vec[b2*3+2];
    float dot = ax*bx + ay*by + az*bz;
    float n1 = sqrtf(ax*ax + ay*ay + az*az);
    float n2 = sqrtf(bx*bx + by*by + bz*bz);
    float c = dot / (n1 * n2 + 1e-9f);
    c = fminf(fmaxf(c, -0.999999f), 0.999999f);
    float angv = acosf(c);
    #pragma unroll
    for (int s = 0; s < CNS; s++) g_cbf[t*CNS + s] = cosf((float)s * angv);
}

// h = silu(concat(atom_emb[atype], noise) @ W_hz), K = 129
__global__ void h0_kernel(const float* __restrict__ atom_emb, const float* __restrict__ W_hz,
                          const float* __restrict__ noise, const int* __restrict__ atype)
{
    __shared__ float emb[128];
    int n = blockIdx.x, j = threadIdx.x;
    emb[j] = atom_emb[atype[n] * 128 + j];
    __syncthreads();
    float acc = noise[n >> 5] * W_hz[128 * 128 + j];
    #pragma unroll 8
    for (int k = 0; k < 128; k++) acc = fmaf(emb[k], W_hz[k * 128 + j], acc);
    g_h[n * 128 + j] = siluf(acc);
}

// m = silu(Hs0[src] + Hd0[dst] + G)   (G staged in g_R)
__global__ void minit_kernel(const int* __restrict__ ei)
{
    int idx = blockIdx.x * blockDim.x + threadIdx.x;  // < CE*128
    int e = idx >> 7, j = idx & 127;
    int s = ei[e], d = ei[CE + e];
    g_m[idx] = siluf(g_hs[s*128 + j] + g_ht[d*128 + j] + g_R[idx]);
}

// m += silu(hs[src] + ht[dst])
__global__ void mupd_kernel(const int* __restrict__ ei)
{
    int idx = blockIdx.x * blockDim.x + threadIdx.x;
    int e = idx >> 7, j = idx & 127;
    int s = ei[e], d = ei[CE + e];
    g_m[idx] += siluf(g_hs[s*128 + j] + g_ht[d*128 + j]);
}

// t = X[id3_kj] * (cbf @ Wcbf[b]); scatter-add into S by id3_ji.
// One block = 4 triplets x 64 outputs.
__global__ void triplet_kernel(const float* __restrict__ Wc,
                               const int* __restrict__ ji, const int* __restrict__ kj)
{
    __shared__ float ws[CNS * 64];   // 1024
    __shared__ float cs[4 * CNS];    // 64
    int tid = threadIdx.x;
    #pragma unroll
    for (int i = 0; i < 4; i++) ws[tid + 256 * i] = Wc[tid + 256 * i];
    int t0 = blockIdx.x << 2;
    if (tid < 64) cs[tid] = g_cbf[(t0 << 4) + tid];
    __syncthreads();
    int lt = tid >> 6, d = tid & 63;
    int t = t0 + lt;
    float acc = 0.0f;
    #pragma unroll
    for (int s = 0; s < CNS; s++)
        acc = fmaf(cs[(lt << 4) + s], ws[(s << 6) + d], acc);
    float val = acc * g_X[kj[t] * 64 + d];
    atomicAdd(&g_S[ji[t] * 64 + d], val);
}

// a[dst] += P  (segment sum by dst)
__global__ void scatter_a_kernel(const int* __restrict__ ei)
{
    int idx = blockIdx.x * blockDim.x + threadIdx.x;  // < CE*128
    int e = idx >> 7, j = idx & 127;
    atomicAdd(&g_a[ei[CE + e] * 128 + j], g_P[idx]);
}

// z = batch-mean of hW (staged in g_hs)
__global__ void z_kernel()
{
    int b = blockIdx.x, j = threadIdx.x;
    float s = 0.0f;
    #pragma unroll
    for (int i = 0; i < CNA; i++) s += g_hs[(b * CNA + i) * 128 + j];
    g_z[b * 128 + j] = s * (1.0f / (float)CNA);
}

__global__ void fc0_kernel(const float* __restrict__ W, const float* __restrict__ bias)
{
    __shared__ float zr[CLAT];
    int b = blockIdx.x, j = threadIdx.x;
    if (j < CLAT) zr[j] = g_z[b * CLAT + j];
    __syncthreads();
    float acc = bias[j];
    #pragma unroll 8
    for (int k = 0; k < CLAT; k++) acc = fmaf(zr[k], W[k * CHID + j], acc);
    g_x1[b * CHID + j] = fmaxf(acc, 0.0f);
}

__global__ void fc1_kernel(const float* __restrict__ W, const float* __restrict__ bias)
{
    __shared__ float xr[CHID];
    int b = blockIdx.x, j = threadIdx.x;
    xr[j] = g_x1[b * CHID + j];
    __syncthreads();
    float acc = bias[j];
    #pragma unroll 8
    for (int k = 0; k < CHID; k++) acc = fmaf(xr[k], W[k * CHID + j], acc);
    g_x2[b * CHID + j] = fmaxf(acc, 0.0f);
}

__global__ void fc2_kernel(const float* __restrict__ W, const float* __restrict__ bias,
                           float* __restrict__ out)
{
    __shared__ float xr[CHID];
    int b = blockIdx.x, j = threadIdx.x;
    xr[j] = g_x2[b * CHID + j];
    __syncthreads();
    if (j >= CNC) return;
    float acc = bias[j];
    #pragma unroll 8
    for (int k = 0; k < CHID; k++) acc = fmaf(xr[k], W[k * CNC + j], acc);
    out[b * CNC + j] = acc;
}

// ============================================================
extern "C" void kernel_launch(void* const* d_in, const int* in_sizes, int n_in,
                              void* d_out, int out_size)
{
    const float *noise, *frac, *lengths, *angles, *atom_emb, *W_hz, *W_edge;
    const float *Wm, *Wr1, *Wdown, *Wcbf, *Wup, *Wa, *Wr2, *Wh, *Ws, *Wt;
    const float *W_out, *W_fc0, *b_fc0, *W_fc1, *b_fc1, *W_fc2, *b_fc2;
    const int *atom_types, *edge_index, *id3_ji, *id3_kj;

    noise   = (const float*)d_in[0];
    frac    = (const float*)d_in[1];
    lengths = (const float*)d_in[2];
    angles  = (const float*)d_in[3];
    if (in_sizes[4] == CN) {
        // setup_inputs dict order
        atom_types = (const int*)d_in[4];
        edge_index = (const int*)d_in[6];
        id3_ji     = (const int*)d_in[7];
        id3_kj     = (const int*)d_in[8];
        atom_emb = (const float*)d_in[9];  W_hz  = (const float*)d_in[10];
        W_edge  = (const float*)d_in[11];  Wm    = (const float*)d_in[12];
        Wr1     = (const float*)d_in[13];  Wdown = (const float*)d_in[14];
        Wcbf    = (const float*)d_in[15];  Wup   = (const float*)d_in[16];
        Wa      = (const float*)d_in[17];  Wr2   = (const float*)d_in[18];
        Wh      = (const float*)d_in[19];  Ws    = (const float*)d_in[20];
        Wt      = (const float*)d_in[21];  W_out = (const float*)d_in[22];
        W_fc0   = (const float*)d_in[23];  b_fc0 = (const float*)d_in[24];
        W_fc1   = (const float*)d_in[25];  b_fc1 = (const float*)d_in[26];
        W_fc2   = (const float*)d_in[27];  b_fc2 = (const float*)d_in[28];
    } else {
        // reference() signature order
        atom_emb = (const float*)d_in[4];  W_hz  = (const float*)d_in[5];
        W_edge  = (const float*)d_in[6];   Wm    = (const float*)d_in[7];
        Wr1     = (const float*)d_in[8];   Wdown = (const float*)d_in[9];
        Wcbf    = (const float*)d_in[10];  Wup   = (const float*)d_in[11];
        Wa      = (const float*)d_in[12];  Wr2   = (const float*)d_in[13];
        Wh      = (const float*)d_in[14];  Ws    = (const float*)d_in[15];
        Wt      = (const float*)d_in[16];  W_out = (const float*)d_in[17];
        W_fc0   = (const float*)d_in[18];  b_fc0 = (const float*)d_in[19];
        W_fc1   = (const float*)d_in[20];  b_fc1 = (const float*)d_in[21];
        W_fc2   = (const float*)d_in[22];  b_fc2 = (const float*)d_in[23];
        atom_types = (const int*)d_in[24];
        edge_index = (const int*)d_in[26];
        id3_ji     = (const int*)d_in[27];
        id3_kj     = (const int*)d_in[28];
    }

    float *p_h, *p_hs, *p_ht, *p_a, *p_m, *p_P, *p_R, *p_X, *p_S, *p_rbf;
    cudaGetSymbolAddress((void**)&p_h,  g_h);
    cudaGetSymbolAddress((void**)&p_hs, g_hs);
    cudaGetSymbolAddress((void**)&p_ht, g_ht);
    cudaGetSymbolAddress((void**)&p_a,  g_a);
    cudaGetSymbolAddress((void**)&p_m,  g_m);
    cudaGetSymbolAddress((void**)&p_P,  g_P);
    cudaGetSymbolAddress((void**)&p_R,  g_R);
    cudaGetSymbolAddress((void**)&p_X,  g_X);
    cudaGetSymbolAddress((void**)&p_S,  g_S);
    cudaGetSymbolAddress((void**)&p_rbf, g_rbf);

    // ---- geometry / features ----
    pos_kernel<<<CN/256, 256>>>(frac, lengths, angles);
    vec_kernel<<<CE/256, 256>>>(edge_index);
    rbf_kernel<<<(CE*CNR)/256, 256>>>();
    cbf_kernel<<<CT/256, 256>>>(id3_ji, id3_kj);
    h0_kernel<<<CN, 128>>>(atom_emb, W_hz, noise, atom_types);

    dim3 gEE(CEE/64, CE/128);   // E x 128
    dim3 gED(CDT/64, CE/128);   // E x 64
    dim3 gNN(CEE/64, CN/128);   // N x 128

    // ---- m init: split W_edge into W1(h_src) | W2(h_dst) | W3(rbf) ----
    gemm_tf32<0><<<gNN, 128>>>(p_h, W_edge,            nullptr, p_hs, CN, CEE, CEA);
    gemm_tf32<0><<<gNN, 128>>>(p_h, W_edge + 128*CEE,  nullptr, p_ht, CN, CEE, CEA);
    gemm_tf32<0><<<gEE, 128>>>(p_rbf, W_edge + 256*CEE, nullptr, p_R, CE, CEE, CNR);
    minit_kernel<<<(CE*CEE)/256, 256>>>(edge_index);

    for (int b = 0; b < 3; b++) {
        const float* Wm_b    = Wm    + b*CEE*CEE;
        const float* Wr1_b   = Wr1   + b*CNR*CEE;
        const float* Wdown_b = Wdown + b*CEE*CDT;
        const float* Wcbf_b  = Wcbf  + b*CNS*CDT;
        const float* Wup_b   = Wup   + b*CDT*CEE;
        const float* Wa_b    = Wa    + b*CEE*CEA;
        const float* Wr2_b   = Wr2   + b*CNR*CEA;
        const float* Wh_b    = Wh    + b*CEA*CEA;
        const float* Ws_b    = Ws    + b*CEA*CEE;
        const float* Wt_b    = Wt    + b*CEA*CEE;

        // x = (silu(m@Wm) * (rbf@Wr1)) @ Wdown
        gemm_tf32<0><<<gEE, 128>>>(p_rbf, Wr1_b, nullptr, p_R, CE, CEE, CNR);
        gemm_tf32<1><<<gEE, 128>>>(p_m,   Wm_b,  p_R,     p_P, CE, CEE, CEE);
        gemm_tf32<0><<<gED, 128>>>(p_P,   Wdown_b, nullptr, p_X, CE, CDT, CEE);

        // t = x[id3_kj] * (cbf@Wcbf); S = seg(t, id3_ji); m += silu(S@Wup)
        zero_k<<<(CE*CDT)/256, 256>>>(p_S, CE*CDT);
        triplet_kernel<<<CT/4, 256>>>(Wcbf_b, id3_ji, id3_kj);
        gemm_tf32<2><<<gEE, 128>>>(p_S, Wup_b, nullptr, p_m, CE, CEE, CDT);

        // a = seg(silu(m@Wa) * (rbf@Wr2), dst); h += silu(a@Wh)
        gemm_tf32<0><<<gEE, 128>>>(p_rbf, Wr2_b, nullptr, p_R, CE, CEA, CNR);
        gemm_tf32<1><<<gEE, 128>>>(p_m,   Wa_b,  p_R,     p_P, CE, CEA, CEE);
        zero_k<<<(CN*CEA)/256, 256>>>(p_a, CN*CEA);
        scatter_a_kernel<<<(CE*CEA)/256, 256>>>(edge_index);
        gemm_tf32<2><<<gNN, 128>>>(p_a, Wh_b, nullptr, p_h, CN, CEA, CEA);

        // m += silu(h[src]@Ws + h[dst]@Wt)
        gemm_tf32<0><<<gNN, 128>>>(p_h, Ws_b, nullptr, p_hs, CN, CEE, CEA);
        gemm_tf32<0><<<gNN, 128>>>(p_h, Wt_b, nullptr, p_ht, CN, CEE, CEA);
        mupd_kernel<<<(CE*CEE)/256, 256>>>(edge_index);
    }

    // ---- readout ----
    gemm_tf32<0><<<dim3(CLAT/64, CN/128), 128>>>(p_h, W_out, nullptr, p_hs, CN, CLAT, CEA);
    z_kernel<<<CB, CLAT>>>();
    fc0_kernel<<<CB, CHID>>>(W_fc0, b_fc0);
    fc1_kernel<<<CB, CHID>>>(W_fc1, b_fc1);
    fc2_kernel<<<CB, CHID>>>(W_fc2, b_fc2, (float*)d_out);
}

// round 6
// speedup vs baseline: 1.0003x; 1.0003x over previous
#include <cuda_runtime.h>
#include <math.h>
#include <stdint.h>

// ---- problem constants ----
#define CB   128
#define CNA  32
#define CN   4096      // atoms
#define CE   65536     // edges
#define CT   262144    // triplets
#define CNR  64
#define CNS  16
#define CEA  128
#define CEE  128
#define CDT  64
#define CLAT 128
#define CHID 256
#define CNC  230

// ---- scratch (device globals: no allocation allowed) ----
__device__ float g_pos[CN*3];
__device__ float g_vec[CE*3];
__device__ float g_rbf[CE*CNR];
__device__ float g_cbf[CT*CNS];
__device__ float g_h [CN*CEA];
__device__ float g_hs[CN*CEA];
__device__ float g_ht[CN*CEA];
__device__ float g_a [CN*CEA];
__device__ float g_m [CE*CEE];
__device__ float g_P [CE*CEE];
__device__ float g_R [CE*CEE];
__device__ float g_X [CE*CDT];
__device__ float g_S [CE*CDT];
__device__ float g_z [CB*CLAT];
__device__ float g_x1[CB*CHID];
__device__ float g_x2[CB*CHID];

__device__ __forceinline__ float siluf(float x) { return x / (1.0f + expf(-x)); }

__device__ __forceinline__ uint32_t f2tf32(float x) {
    uint32_t r;
    asm("cvt.rna.tf32.f32 %0, %1;" : "=r"(r) : "f"(x));
    return r;
}

__device__ __forceinline__ void mma_tf32(float c[4], const uint32_t a[4], const uint32_t b[2]) {
    asm volatile(
        "mma.sync.aligned.m16n8k8.row.col.f32.tf32.tf32.f32 "
        "{%0,%1,%2,%3}, {%4,%5,%6,%7}, {%8,%9}, {%0,%1,%2,%3};"
        : "+f"(c[0]), "+f"(c[1]), "+f"(c[2]), "+f"(c[3])
        : "r"(a[0]), "r"(a[1]), "r"(a[2]), "r"(a[3]), "r"(b[0]), "r"(b[1]));
}

// ============================================================
// TF32 tensor-core GEMM: C[M,N] = epi(A[M,K] @ Bw[K,N])
// CTA tile 128x64, 4 warps (2x2), warp tile 64x32, BK=16,
// double-buffered smem, XOR-swizzled A tile.
// Requires: M%128==0, N%64==0, K%16==0 (true for all calls here).
// EPI 0: C = acc
// EPI 1: C = silu(acc) * D
// EPI 2: C += silu(acc)
// ============================================================
template<int EPI>
__global__ void __launch_bounds__(128)
gemm_tf32(const float* __restrict__ A, const float* __restrict__ Bw,
          const float* __restrict__ D, float* __restrict__ C,
          int M, int N, int K)
{
    __shared__ uint32_t As[2][16][136];  // [buf][k][m swizzled], stride 136 -> bank = 8k+m
    __shared__ uint32_t Bs[2][16][72];   // [buf][k][n], stride 72 -> bank = 8k+n

    const int tid  = threadIdx.x;
    const int lane = tid & 31;
    const int wid  = tid >> 5;
    const int wm   = (wid & 1) * 64;
    const int wn   = (wid >> 1) * 32;
    const int m0   = blockIdx.y * 128;
    const int n0   = blockIdx.x * 64;
    const int nk   = K >> 4;

    // A-load geometry: thread owns row (tid>>2)+32q, float4 at f4*4 within BK
    const int arow = tid >> 2;
    const int af4  = tid & 3;
    // B-load geometry: thread owns k=(tid>>4)+8r, 4 floats at (tid&15)*4
    const int bk   = tid >> 4;
    const int bn4  = (tid & 15) << 2;

    float4 areg[4];
    float4 breg[2];

    auto gload = [&](int k0) {
        #pragma unroll
        for (int q = 0; q < 4; q++) {
            int m = q * 32 + arow;
            areg[q] = *reinterpret_cast<const float4*>(A + (size_t)(m0 + m) * K + k0 + af4 * 4);
        }
        #pragma unroll
        for (int r = 0; r < 2; r++) {
            int k = bk + r * 8;
            breg[r] = *reinterpret_cast<const float4*>(Bw + (size_t)(k0 + k) * N + n0 + bn4);
        }
    };

    auto ssave = [&](int buf) {
        // A: k rows af4*4..af4*4+3, logical col m, physical col m ^ (af4<<3)
        #pragma unroll
        for (int q = 0; q < 4; q++) {
            int m  = q * 32 + arow;
            int mc = m ^ (af4 << 3);
            As[buf][af4 * 4 + 0][mc] = f2tf32(areg[q].x);
            As[buf][af4 * 4 + 1][mc] = f2tf32(areg[q].y);
            As[buf][af4 * 4 + 2][mc] = f2tf32(areg[q].z);
            As[buf][af4 * 4 + 3][mc] = f2tf32(areg[q].w);
        }
        #pragma unroll
        for (int r = 0; r < 2; r++) {
            int k = bk + r * 8;
            uint4 v;
            v.x = f2tf32(breg[r].x); v.y = f2tf32(breg[r].y);
            v.z = f2tf32(breg[r].z); v.w = f2tf32(breg[r].w);
            *reinterpret_cast<uint4*>(&Bs[buf][k][bn4]) = v;
        }
    };

    float acc[4][4][4] = {};

    gload(0);
    ssave(0);
    __syncthreads();

    for (int kb = 0; kb < nk; kb++) {
        int cur = kb & 1;
        if (kb + 1 < nk) gload((kb + 1) << 4);

        #pragma unroll
        for (int kt = 0; kt < 2; kt++) {
            uint32_t af[4][4], bf[4][2];
            int kr  = kt * 8 + (lane & 3);
            int sw0 = ((kr >> 2) & 3) << 3;
            int sw1 = (((kr + 4) >> 2) & 3) << 3;
            #pragma unroll
            for (int mt = 0; mt < 4; mt++) {
                int m = wm + mt * 16 + (lane >> 2);
                af[mt][0] = As[cur][kr    ][m       ^ sw0];
                af[mt][1] = As[cur][kr    ][(m + 8) ^ sw0];
                af[mt][2] = As[cur][kr + 4][m       ^ sw1];
                af[mt][3] = As[cur][kr + 4][(m + 8) ^ sw1];
            }
            #pragma unroll
            for (int nt = 0; nt < 4; nt++) {
                int n = wn + nt * 8 + (lane >> 2);
                bf[nt][0] = Bs[cur][kr    ][n];
                bf[nt][1] = Bs[cur][kr + 4][n];
            }
            #pragma unroll
            for (int mt = 0; mt < 4; mt++)
                #pragma unroll
                for (int nt = 0; nt < 4; nt++)
                    mma_tf32(acc[mt][nt], af[mt], bf[nt]);
        }

        if (kb + 1 < nk) ssave(cur ^ 1);
        __syncthreads();
    }

    // Epilogue
    #pragma unroll
    for (int mt = 0; mt < 4; mt++) {
        #pragma unroll
        for (int nt = 0; nt < 4; nt++) {
            int row = m0 + wm + mt * 16 + (lane >> 2);
            int col = n0 + wn + nt * 8 + ((lane & 3) << 1);
            size_t i0 = (size_t)row * N + col;
            size_t i1 = (size_t)(row + 8) * N + col;
            float2 v0 = make_float2(acc[mt][nt][0], acc[mt][nt][1]);
            float2 v1 = make_float2(acc[mt][nt][2], acc[mt][nt][3]);
            if (EPI == 0) {
                *reinterpret_cast<float2*>(C + i0) = v0;
                *reinterpret_cast<float2*>(C + i1) = v1;
            } else if (EPI == 1) {
                float2 d0 = *reinterpret_cast<const float2*>(D + i0);
                float2 d1 = *reinterpret_cast<const float2*>(D + i1);
                v0.x = siluf(v0.x) * d0.x; v0.y = siluf(v0.y) * d0.y;
                v1.x = siluf(v1.x) * d1.x; v1.y = siluf(v1.y) * d1.y;
                *reinterpret_cast<float2*>(C + i0) = v0;
                *reinterpret_cast<float2*>(C + i1) = v1;
            } else {
                float2 c0 = *reinterpret_cast<const float2*>(C + i0);
                float2 c1 = *reinterpret_cast<const float2*>(C + i1);
                c0.x += siluf(v0.x); c0.y += siluf(v0.y);
                c1.x += siluf(v1.x); c1.y += siluf(v1.y);
                *reinterpret_cast<float2*>(C + i0) = c0;
                *reinterpret_cast<float2*>(C + i1) = c1;
            }
        }
    }
}

__global__ void zero_k(float* __restrict__ p, int n)
{
    int i = blockIdx.x * blockDim.x + threadIdx.x;
    if (i < n) p[i] = 0.0f;
}

// ---- geometry ----
__global__ void pos_kernel(const float* __restrict__ frac, const float* __restrict__ len,
                           const float* __restrict__ ang)
{
    int n = blockIdx.x * blockDim.x + threadIdx.x;
    if (n >= CN) return;
    int b = n >> 5;
    const float D2R = 0.017453292519943295f;
    float La = len[b*3+0], Lb = len[b*3+1], Lc = len[b*3+2];
    float al = ang[b*3+0]*D2R, be = ang[b*3+1]*D2R, ga = ang[b*3+2]*D2R;
    float ca = cosf(al), cb = cosf(be), cg = cosf(ga), sg = sinf(ga);
    float v1x = La;
    float v2x = Lb * cg, v2y = Lb * sg;
    float cx = cb;
    float cy = (ca - cb * cg) / sg;
    float cz = sqrtf(fmaxf(1.0f - cx*cx - cy*cy, 1e-8f));
    float v3x = Lc * cx, v3y = Lc * cy, v3z = Lc * cz;
    float f0 = frac[n*3+0], f1 = frac[n*3+1], f2 = frac[n*3+2];
    g_pos[n*3+0] = f0*v1x + f1*v2x + f2*v3x;
    g_pos[n*3+1] = f1*v2y + f2*v3y;
    g_pos[n*3+2] = f2*v3z;
}

__global__ void vec_kernel(const int* __restrict__ ei)
{
    int e = blockIdx.x * blockDim.x + threadIdx.x;
    if (e >= CE) return;
    int s = ei[e], d = ei[CE + e];
    g_vec[e*3+0] = g_pos[d*3+0] - g_pos[s*3+0];
    g_vec[e*3+1] = g_pos[d*3+1] - g_pos[s*3+1];
    g_vec[e*3+2] = g_pos[d*3+2] - g_pos[s*3+2];
}

__global__ void rbf_kernel()
{
    int idx = blockIdx.x * blockDim.x + threadIdx.x;  // < CE*64
    int e = idx >> 6, r = idx & 63;
    float vx = g_vec[e*3+0], vy = g_vec[e*3+1], vz = g_vec[e*3+2];
    float d = sqrtf(vx*vx + vy*vy + vz*vz + 1e-12f);
    float ds = d * (1.0f / 7.0f);
    float env = 0.0f;
    if (ds < 1.0f) {
        float ds2 = ds*ds, ds4 = ds2*ds2, ds5 = ds4*ds;
        float ds6 = ds5*ds, ds7 = ds6*ds;
        env = 1.0f - 21.0f*ds5 + 35.0f*ds6 - 15.0f*ds7;
    }
    float nn = (float)(r + 1);
    g_rbf[idx] = env * 0.5345224838248488f * sinf(nn * 3.14159265358979323846f * ds) / d;
}

__global__ void cbf_kernel(const int* __restrict__ ji, const int* __restrict__ kj)
{
    int t = blockIdx.x * blockDim.x + threadIdx.x;
    if (t >= CT) return;
    int a = ji[t], b2 = kj[t];
    float ax = g_vec[a*3+0], ay = g_vec[a*3+1], az = g_vec[a*3+2];
    float bx = g_vec[b2*3+0], by = g_vec[b2*3+1], bz = g_vec[b2*3+2];
    float dot = ax*bx + ay*by + az*bz;
    float n1 = sqrtf(ax*ax + ay*ay + az*az);
    float n2 = sqrtf(bx*bx + by*by + bz*bz);
    float c = dot / (n1 * n2 + 1e-9f);
    c = fminf(fmaxf(c, -0.999999f), 0.999999f);
    float angv = acosf(c);
    #pragma unroll
    for (int s = 0; s < CNS; s++) g_cbf[t*CNS + s] = cosf((float)s * angv);
}

// h = silu(concat(atom_emb[atype], noise) @ W_hz), K = 129
__global__ void h0_kernel(const float* __restrict__ atom_emb, const float* __restrict__ W_hz,
                          const float* __restrict__ noise, const int* __restrict__ atype)
{
    __shared__ float emb[128];
    int n = blockIdx.x, j = threadIdx.x;
    emb[j] = atom_emb[atype[n] * 128 + j];
    __syncthreads();
    float acc = noise[n >> 5] * W_hz[128 * 128 + j];
    #pragma unroll 8
    for (int k = 0; k < 128; k++) acc = fmaf(emb[k], W_hz[k * 128 + j], acc);
    g_h[n * 128 + j] = siluf(acc);
}

// m = silu(Hs0[src] + Hd0[dst] + G)   (G staged in g_R)
__global__ void minit_kernel(const int* __restrict__ ei)
{
    int idx = blockIdx.x * blockDim.x + threadIdx.x;  // < CE*128
    int e = idx >> 7, j = idx & 127;
    int s = ei[e], d = ei[CE + e];
    g_m[idx] = siluf(g_hs[s*128 + j] + g_ht[d*128 + j] + g_R[idx]);
}

// m += silu(hs[src] + ht[dst])
__global__ void mupd_kernel(const int* __restrict__ ei)
{
    int idx = blockIdx.x * blockDim.x + threadIdx.x;
    int e = idx >> 7, j = idx & 127;
    int s = ei[e], d = ei[CE + e];
    g_m[idx] += siluf(g_hs[s*128 + j] + g_ht[d*128 + j]);
}

// t = X[id3_kj] * (cbf @ Wcbf[b]); scatter-add into S by id3_ji.
// One block = 4 triplets x 64 outputs.
__global__ void triplet_kernel(const float* __restrict__ Wc,
                               const int* __restrict__ ji, const int* __restrict__ kj)
{
    __shared__ float ws[CNS * 64];   // 1024
    __shared__ float cs[4 * CNS];    // 64
    int tid = threadIdx.x;
    #pragma unroll
    for (int i = 0; i < 4; i++) ws[tid + 256 * i] = Wc[tid + 256 * i];
    int t0 = blockIdx.x << 2;
    if (tid < 64) cs[tid] = g_cbf[(t0 << 4) + tid];
    __syncthreads();
    int lt = tid >> 6, d = tid & 63;
    int t = t0 + lt;
    float acc = 0.0f;
    #pragma unroll
    for (int s = 0; s < CNS; s++)
        acc = fmaf(cs[(lt << 4) + s], ws[(s << 6) + d], acc);
    float val = acc * g_X[kj[t] * 64 + d];
    atomicAdd(&g_S[ji[t] * 64 + d], val);
}

// a[dst] += P  (segment sum by dst)
__global__ void scatter_a_kernel(const int* __restrict__ ei)
{
    int idx = blockIdx.x * blockDim.x + threadIdx.x;  // < CE*128
    int e = idx >> 7, j = idx & 127;
    atomicAdd(&g_a[ei[CE + e] * 128 + j], g_P[idx]);
}

// z = batch-mean of hW (staged in g_hs)
__global__ void z_kernel()
{
    int b = blockIdx.x, j = threadIdx.x;
    float s = 0.0f;
    #pragma unroll
    for (int i = 0; i < CNA; i++) s += g_hs[(b * CNA + i) * 128 + j];
    g_z[b * 128 + j] = s * (1.0f / (float)CNA);
}

__global__ void fc0_kernel(const float* __restrict__ W, const float* __restrict__ bias)
{
    __shared__ float zr[CLAT];
    int b = blockIdx.x, j = threadIdx.x;
    if (j < CLAT) zr[j] = g_z[b * CLAT + j];
    __syncthreads();
    float acc = bias[j];
    #pragma unroll 8
    for (int k = 0; k < CLAT; k++) acc = fmaf(zr[k], W[k * CHID + j], acc);
    g_x1[b * CHID + j] = fmaxf(acc, 0.0f);
}

__global__ void fc1_kernel(const float* __restrict__ W, const float* __restrict__ bias)
{
    __shared__ float xr[CHID];
    int b = blockIdx.x, j = threadIdx.x;
    xr[j] = g_x1[b * CHID + j];
    __syncthreads();
    float acc = bias[j];
    #pragma unroll 8
    for (int k = 0; k < CHID; k++) acc = fmaf(xr[k], W[k * CHID + j], acc);
    g_x2[b * CHID + j] = fmaxf(acc, 0.0f);
}

__global__ void fc2_kernel(const float* __restrict__ W, const float* __restrict__ bias,
                           float* __restrict__ out)
{
    __shared__ float xr[CHID];
    int b = blockIdx.x, j = threadIdx.x;
    xr[j] = g_x2[b * CHID + j];
    __syncthreads();
    if (j >= CNC) return;
    float acc = bias[j];
    #pragma unroll 8
    for (int k = 0; k < CHID; k++) acc = fmaf(xr[k], W[k * CNC + j], acc);
    out[b * CNC + j] = acc;
}

// ============================================================
extern "C" void kernel_launch(void* const* d_in, const int* in_sizes, int n_in,
                              void* d_out, int out_size)
{
    const float *noise, *frac, *lengths, *angles, *atom_emb, *W_hz, *W_edge;
    const float *Wm, *Wr1, *Wdown, *Wcbf, *Wup, *Wa, *Wr2, *Wh, *Ws, *Wt;
    const float *W_out, *W_fc0, *b_fc0, *W_fc1, *b_fc1, *W_fc2, *b_fc2;
    const int *atom_types, *edge_index, *id3_ji, *id3_kj;

    noise   = (const float*)d_in[0];
    frac    = (const float*)d_in[1];
    lengths = (const float*)d_in[2];
    angles  = (const float*)d_in[3];
    if (in_sizes[4] == CN) {
        // setup_inputs dict order
        atom_types = (const int*)d_in[4];
        edge_index = (const int*)d_in[6];
        id3_ji     = (const int*)d_in[7];
        id3_kj     = (const int*)d_in[8];
        atom_emb = (const float*)d_in[9];  W_hz  = (const float*)d_in[10];
        W_edge  = (const float*)d_in[11];  Wm    = (const float*)d_in[12];
        Wr1     = (const float*)d_in[13];  Wdown = (const float*)d_in[14];
        Wcbf    = (const float*)d_in[15];  Wup   = (const float*)d_in[16];
        Wa      = (const float*)d_in[17];  Wr2   = (const float*)d_in[18];
        Wh      = (const float*)d_in[19];  Ws    = (const float*)d_in[20];
        Wt      = (const float*)d_in[21];  W_out = (const float*)d_in[22];
        W_fc0   = (const float*)d_in[23];  b_fc0 = (const float*)d_in[24];
        W_fc1   = (const float*)d_in[25];  b_fc1 = (const float*)d_in[26];
        W_fc2   = (const float*)d_in[27];  b_fc2 = (const float*)d_in[28];
    } else {
        // reference() signature order
        atom_emb = (const float*)d_in[4];  W_hz  = (const float*)d_in[5];
        W_edge  = (const float*)d_in[6];   Wm    = (const float*)d_in[7];
        Wr1     = (const float*)d_in[8];   Wdown = (const float*)d_in[9];
        Wcbf    = (const float*)d_in[10];  Wup   = (const float*)d_in[11];
        Wa      = (const float*)d_in[12];  Wr2   = (const float*)d_in[13];
        Wh      = (const float*)d_in[14];  Ws    = (const float*)d_in[15];
        Wt      = (const float*)d_in[16];  W_out = (const float*)d_in[17];
        W_fc0   = (const float*)d_in[18];  b_fc0 = (const float*)d_in[19];
        W_fc1   = (const float*)d_in[20];  b_fc1 = (const float*)d_in[21];
        W_fc2   = (const float*)d_in[22];  b_fc2 = (const float*)d_in[23];
        atom_types = (const int*)d_in[24];
        edge_index = (const int*)d_in[26];
        id3_ji     = (const int*)d_in[27];
        id3_kj     = (const int*)d_in[28];
    }

    float *p_h, *p_hs, *p_ht, *p_a, *p_m, *p_P, *p_R, *p_X, *p_S, *p_rbf;
    cudaGetSymbolAddress((void**)&p_h,  g_h);
    cudaGetSymbolAddress((void**)&p_hs, g_hs);
    cudaGetSymbolAddress((void**)&p_ht, g_ht);
    cudaGetSymbolAddress((void**)&p_a,  g_a);
    cudaGetSymbolAddress((void**)&p_m,  g_m);
    cudaGetSymbolAddress((void**)&p_P,  g_P);
    cudaGetSymbolAddress((void**)&p_R,  g_R);
    cudaGetSymbolAddress((void**)&p_X,  g_X);
    cudaGetSymbolAddress((void**)&p_S,  g_S);
    cudaGetSymbolAddress((void**)&p_rbf, g_rbf);

    // ---- geometry / features ----
    pos_kernel<<<CN/256, 256>>>(frac, lengths, angles);
    vec_kernel<<<CE/256, 256>>>(edge_index);
    rbf_kernel<<<(CE*CNR)/256, 256>>>();
    cbf_kernel<<<CT/256, 256>>>(id3_ji, id3_kj);
    h0_kernel<<<CN, 128>>>(atom_emb, W_hz, noise, atom_types);

    dim3 gEE(CEE/64, CE/128);   // E x 128
    dim3 gED(CDT/64, CE/128);   // E x 64
    dim3 gNN(CEE/64, CN/128);   // N x 128

    // ---- m init: split W_edge into W1(h_src) | W2(h_dst) | W3(rbf) ----
    gemm_tf32<0><<<gNN, 128>>>(p_h, W_edge,            nullptr, p_hs, CN, CEE, CEA);
    gemm_tf32<0><<<gNN, 128>>>(p_h, W_edge + 128*CEE,  nullptr, p_ht, CN, CEE, CEA);
    gemm_tf32<0><<<gEE, 128>>>(p_rbf, W_edge + 256*CEE, nullptr, p_R, CE, CEE, CNR);
    minit_kernel<<<(CE*CEE)/256, 256>>>(edge_index);

    for (int b = 0; b < 3; b++) {
        const float* Wm_b    = Wm    + b*CEE*CEE;
        const float* Wr1_b   = Wr1   + b*CNR*CEE;
        const float* Wdown_b = Wdown + b*CEE*CDT;
        const float* Wcbf_b  = Wcbf  + b*CNS*CDT;
        const float* Wup_b   = Wup   + b*CDT*CEE;
        const float* Wa_b    = Wa    + b*CEE*CEA;
        const float* Wr2_b   = Wr2   + b*CNR*CEA;
        const float* Wh_b    = Wh    + b*CEA*CEA;
        const float* Ws_b    = Ws    + b*CEA*CEE;
        const float* Wt_b    = Wt    + b*CEA*CEE;

        // x = (silu(m@Wm) * (rbf@Wr1)) @ Wdown
        gemm_tf32<0><<<gEE, 128>>>(p_rbf, Wr1_b, nullptr, p_R, CE, CEE, CNR);
        gemm_tf32<1><<<gEE, 128>>>(p_m,   Wm_b,  p_R,     p_P, CE, CEE, CEE);
        gemm_tf32<0><<<gED, 128>>>(p_P,   Wdown_b, nullptr, p_X, CE, CDT, CEE);

        // t = x[id3_kj] * (cbf@Wcbf); S = seg(t, id3_ji); m += silu(S@Wup)
        zero_k<<<(CE*CDT)/256, 256>>>(p_S, CE*CDT);
        triplet_kernel<<<CT/4, 256>>>(Wcbf_b, id3_ji, id3_kj);
        gemm_tf32<2><<<gEE, 128>>>(p_S, Wup_b, nullptr, p_m, CE, CEE, CDT);

        // a = seg(silu(m@Wa) * (rbf@Wr2), dst); h += silu(a@Wh)
        gemm_tf32<0><<<gEE, 128>>>(p_rbf, Wr2_b, nullptr, p_R, CE, CEA, CNR);
        gemm_tf32<1><<<gEE, 128>>>(p_m,   Wa_b,  p_R,     p_P, CE, CEA, CEE);
        zero_k<<<(CN*CEA)/256, 256>>>(p_a, CN*CEA);
        scatter_a_kernel<<<(CE*CEA)/256, 256>>>(edge_index);
        gemm_tf32<2><<<gNN, 128>>>(p_a, Wh_b, nullptr, p_h, CN, CEA, CEA);

        // m += silu(h[src]@Ws + h[dst]@Wt)
        gemm_tf32<0><<<gNN, 128>>>(p_h, Ws_b, nullptr, p_hs, CN, CEE, CEA);
        gemm_tf32<0><<<gNN, 128>>>(p_h, Wt_b, nullptr, p_ht, CN, CEE, CEA);
        mupd_kernel<<<(CE*CEE)/256, 256>>>(edge_index);
    }

    // ---- readout ----
    gemm_tf32<0><<<dim3(CLAT/64, CN/128), 128>>>(p_h, W_out, nullptr, p_hs, CN, CLAT, CEA);
    z_kernel<<<CB, CLAT>>>();
    fc0_kernel<<<CB, CHID>>>(W_fc0, b_fc0);
    fc1_kernel<<<CB, CHID>>>(W_fc1, b_fc1);
    fc2_kernel<<<CB, CHID>>>(W_fc2, b_fc2, (float*)d_out);
}

// round 8
// speedup vs baseline: 1.0019x; 1.0015x over previous
#include <cuda_runtime.h>
#include <math.h>
#include <stdint.h>

// ---- problem constants ----
#define CB   128
#define CNA  32
#define CN   4096      // atoms
#define CE   65536     // edges
#define CT   262144    // triplets
#define CNR  64
#define CNS  16
#define CEA  128
#define CEE  128
#define CDT  64
#define CLAT 128
#define CHID 256
#define CNC  230

// ---- scratch (device globals: no allocation allowed) ----
__device__ float g_pos[CN*3];
__device__ float g_vec[CE*3];
__device__ float g_rbf[CE*CNR];
__device__ float g_cbf[CT*CNS];
__device__ float g_h [CN*CEA];
__device__ float g_hs[CN*CEA];
__device__ float g_ht[CN*CEA];
__device__ float g_a [CN*CEA];
__device__ float g_m [CE*CEE];
__device__ float g_P [CE*CEE];
__device__ float g_R [CE*CEE];
__device__ float g_X [CE*CDT];
__device__ float g_S [CE*CDT];
__device__ float g_z [CB*CLAT];
__device__ float g_x1[CB*CHID];
__device__ float g_x2[CB*CHID];

__device__ __forceinline__ float siluf(float x) { return x / (1.0f + expf(-x)); }

__device__ __forceinline__ uint32_t f2tf32(float x) {
    uint32_t r;
    asm("cvt.rna.tf32.f32 %0, %1;" : "=r"(r) : "f"(x));
    return r;
}

__device__ __forceinline__ void mma_tf32(float c[4], const uint32_t a[4], const uint32_t b[2]) {
    asm volatile(
        "mma.sync.aligned.m16n8k8.row.col.f32.tf32.tf32.f32 "
        "{%0,%1,%2,%3}, {%4,%5,%6,%7}, {%8,%9}, {%0,%1,%2,%3};"
        : "+f"(c[0]), "+f"(c[1]), "+f"(c[2]), "+f"(c[3])
        : "r"(a[0]), "r"(a[1]), "r"(a[2]), "r"(a[3]), "r"(b[0]), "r"(b[1]));
}

// ============================================================
// TF32 tensor-core GEMM: C[M,N] = epi(A[M,K] @ Bw[K,N])
// CTA tile 128x64, 4 warps (2x2), warp tile 64x32, BK=16,
// double-buffered smem, XOR-swizzled A tile.
// Requires: M%128==0, N%64==0, K%16==0 (true for all calls here).
// EPI 0: C = acc
// EPI 1: C = silu(acc) * D
// EPI 2: C += silu(acc)
// ============================================================
template<int EPI>
__global__ void __launch_bounds__(128)
gemm_tf32(const float* __restrict__ A, const float* __restrict__ Bw,
          const float* __restrict__ D, float* __restrict__ C,
          int M, int N, int K)
{
    __shared__ uint32_t As[2][16][136];  // [buf][k][m swizzled], stride 136 -> bank = 8k+m
    __shared__ uint32_t Bs[2][16][72];   // [buf][k][n], stride 72 -> bank = 8k+n

    const int tid  = threadIdx.x;
    const int lane = tid & 31;
    const int wid  = tid >> 5;
    const int wm   = (wid & 1) * 64;
    const int wn   = (wid >> 1) * 32;
    const int m0   = blockIdx.y * 128;
    const int n0   = blockIdx.x * 64;
    const int nk   = K >> 4;

    // A-load geometry: thread owns row (tid>>2)+32q, float4 at f4*4 within BK
    const int arow = tid >> 2;
    const int af4  = tid & 3;
    // B-load geometry: thread owns k=(tid>>4)+8r, 4 floats at (tid&15)*4
    const int bk   = tid >> 4;
    const int bn4  = (tid & 15) << 2;

    float4 areg[4];
    float4 breg[2];

    auto gload = [&](int k0) {
        #pragma unroll
        for (int q = 0; q < 4; q++) {
            int m = q * 32 + arow;
            areg[q] = *reinterpret_cast<const float4*>(A + (size_t)(m0 + m) * K + k0 + af4 * 4);
        }
        #pragma unroll
        for (int r = 0; r < 2; r++) {
            int k = bk + r * 8;
            breg[r] = *reinterpret_cast<const float4*>(Bw + (size_t)(k0 + k) * N + n0 + bn4);
        }
    };

    auto ssave = [&](int buf) {
        // A: k rows af4*4..af4*4+3, logical col m, physical col m ^ (af4<<3)
        #pragma unroll
        for (int q = 0; q < 4; q++) {
            int m  = q * 32 + arow;
            int mc = m ^ (af4 << 3);
            As[buf][af4 * 4 + 0][mc] = f2tf32(areg[q].x);
            As[buf][af4 * 4 + 1][mc] = f2tf32(areg[q].y);
            As[buf][af4 * 4 + 2][mc] = f2tf32(areg[q].z);
            As[buf][af4 * 4 + 3][mc] = f2tf32(areg[q].w);
        }
        #pragma unroll
        for (int r = 0; r < 2; r++) {
            int k = bk + r * 8;
            uint4 v;
            v.x = f2tf32(breg[r].x); v.y = f2tf32(breg[r].y);
            v.z = f2tf32(breg[r].z); v.w = f2tf32(breg[r].w);
            *reinterpret_cast<uint4*>(&Bs[buf][k][bn4]) = v;
        }
    };

    float acc[4][4][4] = {};

    gload(0);
    ssave(0);
    __syncthreads();

    for (int kb = 0; kb < nk; kb++) {
        int cur = kb & 1;
        if (kb + 1 < nk) gload((kb + 1) << 4);

        #pragma unroll
        for (int kt = 0; kt < 2; kt++) {
            uint32_t af[4][4], bf[4][2];
            int kr  = kt * 8 + (lane & 3);
            int sw0 = ((kr >> 2) & 3) << 3;
            int sw1 = (((kr + 4) >> 2) & 3) << 3;
            #pragma unroll
            for (int mt = 0; mt < 4; mt++) {
                int m = wm + mt * 16 + (lane >> 2);
                af[mt][0] = As[cur][kr    ][m       ^ sw0];
                af[mt][1] = As[cur][kr    ][(m + 8) ^ sw0];
                af[mt][2] = As[cur][kr + 4][m       ^ sw1];
                af[mt][3] = As[cur][kr + 4][(m + 8) ^ sw1];
            }
            #pragma unroll
            for (int nt = 0; nt < 4; nt++) {
                int n = wn + nt * 8 + (lane >> 2);
                bf[nt][0] = Bs[cur][kr    ][n];
                bf[nt][1] = Bs[cur][kr + 4][n];
            }
            #pragma unroll
            for (int mt = 0; mt < 4; mt++)
                #pragma unroll
                for (int nt = 0; nt < 4; nt++)
                    mma_tf32(acc[mt][nt], af[mt], bf[nt]);
        }

        if (kb + 1 < nk) ssave(cur ^ 1);
        __syncthreads();
    }

    // Epilogue
    #pragma unroll
    for (int mt = 0; mt < 4; mt++) {
        #pragma unroll
        for (int nt = 0; nt < 4; nt++) {
            int row = m0 + wm + mt * 16 + (lane >> 2);
            int col = n0 + wn + nt * 8 + ((lane & 3) << 1);
            size_t i0 = (size_t)row * N + col;
            size_t i1 = (size_t)(row + 8) * N + col;
            float2 v0 = make_float2(acc[mt][nt][0], acc[mt][nt][1]);
            float2 v1 = make_float2(acc[mt][nt][2], acc[mt][nt][3]);
            if (EPI == 0) {
                *reinterpret_cast<float2*>(C + i0) = v0;
                *reinterpret_cast<float2*>(C + i1) = v1;
            } else if (EPI == 1) {
                float2 d0 = *reinterpret_cast<const float2*>(D + i0);
                float2 d1 = *reinterpret_cast<const float2*>(D + i1);
                v0.x = siluf(v0.x) * d0.x; v0.y = siluf(v0.y) * d0.y;
                v1.x = siluf(v1.x) * d1.x; v1.y = siluf(v1.y) * d1.y;
                *reinterpret_cast<float2*>(C + i0) = v0;
                *reinterpret_cast<float2*>(C + i1) = v1;
            } else {
                float2 c0 = *reinterpret_cast<const float2*>(C + i0);
                float2 c1 = *reinterpret_cast<const float2*>(C + i1);
                c0.x += siluf(v0.x); c0.y += siluf(v0.y);
                c1.x += siluf(v1.x); c1.y += siluf(v1.y);
                *reinterpret_cast<float2*>(C + i0) = c0;
                *reinterpret_cast<float2*>(C + i1) = c1;
            }
        }
    }
}

__global__ void zero_k(float* __restrict__ p, int n)
{
    int i = blockIdx.x * blockDim.x + threadIdx.x;
    if (i < n) p[i] = 0.0f;
}

// ---- geometry ----
__global__ void pos_kernel(const float* __restrict__ frac, const float* __restrict__ len,
                           const float* __restrict__ ang)
{
    int n = blockIdx.x * blockDim.x + threadIdx.x;
    if (n >= CN) return;
    int b = n >> 5;
    const float D2R = 0.017453292519943295f;
    float La = len[b*3+0], Lb = len[b*3+1], Lc = len[b*3+2];
    float al = ang[b*3+0]*D2R, be = ang[b*3+1]*D2R, ga = ang[b*3+2]*D2R;
    float ca = cosf(al), cb = cosf(be), cg = cosf(ga), sg = sinf(ga);
    float v1x = La;
    float v2x = Lb * cg, v2y = Lb * sg;
    float cx = cb;
    float cy = (ca - cb * cg) / sg;
    float cz = sqrtf(fmaxf(1.0f - cx*cx - cy*cy, 1e-8f));
    float v3x = Lc * cx, v3y = Lc * cy, v3z = Lc * cz;
    float f0 = frac[n*3+0], f1 = frac[n*3+1], f2 = frac[n*3+2];
    g_pos[n*3+0] = f0*v1x + f1*v2x + f2*v3x;
    g_pos[n*3+1] = f1*v2y + f2*v3y;
    g_pos[n*3+2] = f2*v3z;
}

__global__ void vec_kernel(const int* __restrict__ ei)
{
    int e = blockIdx.x * blockDim.x + threadIdx.x;
    if (e >= CE) return;
    int s = ei[e], d = ei[CE + e];
    g_vec[e*3+0] = g_pos[d*3+0] - g_pos[s*3+0];
    g_vec[e*3+1] = g_pos[d*3+1] - g_pos[s*3+1];
    g_vec[e*3+2] = g_pos[d*3+2] - g_pos[s*3+2];
}

__global__ void rbf_kernel()
{
    int idx = blockIdx.x * blockDim.x + threadIdx.x;  // < CE*64
    int e = idx >> 6, r = idx & 63;
    float vx = g_vec[e*3+0], vy = g_vec[e*3+1], vz = g_vec[e*3+2];
    float d = sqrtf(vx*vx + vy*vy + vz*vz + 1e-12f);
    float ds = d * (1.0f / 7.0f);
    float env = 0.0f;
    if (ds < 1.0f) {
        float ds2 = ds*ds, ds4 = ds2*ds2, ds5 = ds4*ds;
        float ds6 = ds5*ds, ds7 = ds6*ds;
        env = 1.0f - 21.0f*ds5 + 35.0f*ds6 - 15.0f*ds7;
    }
    float nn = (float)(r + 1);
    g_rbf[idx] = env * 0.5345224838248488f * sinf(nn * 3.14159265358979323846f * ds) / d;
}

__global__ void cbf_kernel(const int* __restrict__ ji, const int* __restrict__ kj)
{
    int t = blockIdx.x * blockDim.x + threadIdx.x;
    if (t >= CT) return;
    int a = ji[t], b2 = kj[t];
    float ax = g_vec[a*3+0], ay = g_vec[a*3+1], az = g_vec[a*3+2];
    float bx = g_vec[b2*3+0], by = g_vec[b2*3+1], bz = g_vec[b2*3+2];
    float dot = ax*bx + ay*by + az*bz;
    float n1 = sqrtf(ax*ax + ay*ay + az*az);
    float n2 = sqrtf(bx*bx + by*by + bz*bz);
    float c = dot / (n1 * n2 + 1e-9f);
    c = fminf(fmaxf(c, -0.999999f), 0.999999f);
    float angv = acosf(c);
    #pragma unroll
    for (int s = 0; s < CNS; s++) g_cbf[t*CNS + s] = cosf((float)s * angv);
}

// h = silu(concat(atom_emb[atype], noise) @ W_hz), K = 129
__global__ void h0_kernel(const float* __restrict__ atom_emb, const float* __restrict__ W_hz,
                          const float* __restrict__ noise, const int* __restrict__ atype)
{
    __shared__ float emb[128];
    int n = blockIdx.x, j = threadIdx.x;
    emb[j] = atom_emb[atype[n] * 128 + j];
    __syncthreads();
    float acc = noise[n >> 5] * W_hz[128 * 128 + j];
    #pragma unroll 8
    for (int k = 0; k < 128; k++) acc = fmaf(emb[k], W_hz[k * 128 + j], acc);
    g_h[n * 128 + j] = siluf(acc);
}

// m = silu(Hs0[src] + Hd0[dst] + G)   (G staged in g_R)
__global__ void minit_kernel(const int* __restrict__ ei)
{
    int idx = blockIdx.x * blockDim.x + threadIdx.x;  // < CE*128
    int e = idx >> 7, j = idx & 127;
    int s = ei[e], d = ei[CE + e];
    g_m[idx] = siluf(g_hs[s*128 + j] + g_ht[d*128 + j] + g_R[idx]);
}

// m += silu(hs[src] + ht[dst])
__global__ void mupd_kernel(const int* __restrict__ ei)
{
    int idx = blockIdx.x * blockDim.x + threadIdx.x;
    int e = idx >> 7, j = idx & 127;
    int s = ei[e], d = ei[CE + e];
    g_m[idx] += siluf(g_hs[s*128 + j] + g_ht[d*128 + j]);
}

// t = X[id3_kj] * (cbf @ Wcbf[b]); scatter-add into S by id3_ji.
// One block = 4 triplets x 64 outputs.
__global__ void triplet_kernel(const float* __restrict__ Wc,
                               const int* __restrict__ ji, const int* __restrict__ kj)
{
    __shared__ float ws[CNS * 64];   // 1024
    __shared__ float cs[4 * CNS];    // 64
    int tid = threadIdx.x;
    #pragma unroll
    for (int i = 0; i < 4; i++) ws[tid + 256 * i] = Wc[tid + 256 * i];
    int t0 = blockIdx.x << 2;
    if (tid < 64) cs[tid] = g_cbf[(t0 << 4) + tid];
    __syncthreads();
    int lt = tid >> 6, d = tid & 63;
    int t = t0 + lt;
    float acc = 0.0f;
    #pragma unroll
    for (int s = 0; s < CNS; s++)
        acc = fmaf(cs[(lt << 4) + s], ws[(s << 6) + d], acc);
    float val = acc * g_X[kj[t] * 64 + d];
    atomicAdd(&g_S[ji[t] * 64 + d], val);
}

// a[dst] += P  (segment sum by dst)
__global__ void scatter_a_kernel(const int* __restrict__ ei)
{
    int idx = blockIdx.x * blockDim.x + threadIdx.x;  // < CE*128
    int e = idx >> 7, j = idx & 127;
    atomicAdd(&g_a[ei[CE + e] * 128 + j], g_P[idx]);
}

// z = batch-mean of hW (staged in g_hs)
__global__ void z_kernel()
{
    int b = blockIdx.x, j = threadIdx.x;
    float s = 0.0f;
    #pragma unroll
    for (int i = 0; i < CNA; i++) s += g_hs[(b * CNA + i) * 128 + j];
    g_z[b * 128 + j] = s * (1.0f / (float)CNA);
}

__global__ void fc0_kernel(const float* __restrict__ W, const float* __restrict__ bias)
{
    __shared__ float zr[CLAT];
    int b = blockIdx.x, j = threadIdx.x;
    if (j < CLAT) zr[j] = g_z[b * CLAT + j];
    __syncthreads();
    float acc = bias[j];
    #pragma unroll 8
    for (int k = 0; k < CLAT; k++) acc = fmaf(zr[k], W[k * CHID + j], acc);
    g_x1[b * CHID + j] = fmaxf(acc, 0.0f);
}

__global__ void fc1_kernel(const float* __restrict__ W, const float* __restrict__ bias)
{
    __shared__ float xr[CHID];
    int b = blockIdx.x, j = threadIdx.x;
    xr[j] = g_x1[b * CHID + j];
    __syncthreads();
    float acc = bias[j];
    #pragma unroll 8
    for (int k = 0; k < CHID; k++) acc = fmaf(xr[k], W[k * CHID + j], acc);
    g_x2[b * CHID + j] = fmaxf(acc, 0.0f);
}

__global__ void fc2_kernel(const float* __restrict__ W, const float* __restrict__ bias,
                           float* __restrict__ out)
{
    __shared__ float xr[CHID];
    int b = blockIdx.x, j = threadIdx.x;
    xr[j] = g_x2[b * CHID + j];
    __syncthreads();
    if (j >= CNC) return;
    float acc = bias[j];
    #pragma unroll 8
    for (int k = 0; k < CHID; k++) acc = fmaf(xr[k], W[k * CNC + j], acc);
    out[b * CNC + j] = acc;
}

// ============================================================
extern "C" void kernel_launch(void* const* d_in, const int* in_sizes, int n_in,
                              void* d_out, int out_size)
{
    const float *noise, *frac, *lengths, *angles, *atom_emb, *W_hz, *W_edge;
    const float *Wm, *Wr1, *Wdown, *Wcbf, *Wup, *Wa, *Wr2, *Wh, *Ws, *Wt;
    const float *W_out, *W_fc0, *b_fc0, *W_fc1, *b_fc1, *W_fc2, *b_fc2;
    const int *atom_types, *edge_index, *id3_ji, *id3_kj;

    noise   = (const float*)d_in[0];
    frac    = (const float*)d_in[1];
    lengths = (const float*)d_in[2];
    angles  = (const float*)d_in[3];
    if (in_sizes[4] == CN) {
        // setup_inputs dict order
        atom_types = (const int*)d_in[4];
        edge_index = (const int*)d_in[6];
        id3_ji     = (const int*)d_in[7];
        id3_kj     = (const int*)d_in[8];
        atom_emb = (const float*)d_in[9];  W_hz  = (const float*)d_in[10];
        W_edge  = (const float*)d_in[11];  Wm    = (const float*)d_in[12];
        Wr1     = (const float*)d_in[13];  Wdown = (const float*)d_in[14];
        Wcbf    = (const float*)d_in[15];  Wup   = (const float*)d_in[16];
        Wa      = (const float*)d_in[17];  Wr2   = (const float*)d_in[18];
        Wh      = (const float*)d_in[19];  Ws    = (const float*)d_in[20];
        Wt      = (const float*)d_in[21];  W_out = (const float*)d_in[22];
        W_fc0   = (const float*)d_in[23];  b_fc0 = (const float*)d_in[24];
        W_fc1   = (const float*)d_in[25];  b_fc1 = (const float*)d_in[26];
        W_fc2   = (const float*)d_in[27];  b_fc2 = (const float*)d_in[28];
    } else {
        // reference() signature order
        atom_emb = (const float*)d_in[4];  W_hz  = (const float*)d_in[5];
        W_edge  = (const float*)d_in[6];   Wm    = (const float*)d_in[7];
        Wr1     = (const float*)d_in[8];   Wdown = (const float*)d_in[9];
        Wcbf    = (const float*)d_in[10];  Wup   = (const float*)d_in[11];
        Wa      = (const float*)d_in[12];  Wr2   = (const float*)d_in[13];
        Wh      = (const float*)d_in[14];  Ws    = (const float*)d_in[15];
        Wt      = (const float*)d_in[16];  W_out = (const float*)d_in[17];
        W_fc0   = (const float*)d_in[18];  b_fc0 = (const float*)d_in[19];
        W_fc1   = (const float*)d_in[20];  b_fc1 = (const float*)d_in[21];
        W_fc2   = (const float*)d_in[22];  b_fc2 = (const float*)d_in[23];
        atom_types = (const int*)d_in[24];
        edge_index = (const int*)d_in[26];
        id3_ji     = (const int*)d_in[27];
        id3_kj     = (const int*)d_in[28];
    }

    float *p_h, *p_hs, *p_ht, *p_a, *p_m, *p_P, *p_R, *p_X, *p_S, *p_rbf;
    cudaGetSymbolAddress((void**)&p_h,  g_h);
    cudaGetSymbolAddress((void**)&p_hs, g_hs);
    cudaGetSymbolAddress((void**)&p_ht, g_ht);
    cudaGetSymbolAddress((void**)&p_a,  g_a);
    cudaGetSymbolAddress((void**)&p_m,  g_m);
    cudaGetSymbolAddress((void**)&p_P,  g_P);
    cudaGetSymbolAddress((void**)&p_R,  g_R);
    cudaGetSymbolAddress((void**)&p_X,  g_X);
    cudaGetSymbolAddress((void**)&p_S,  g_S);
    cudaGetSymbolAddress((void**)&p_rbf, g_rbf);

    // ---- geometry / features ----
    pos_kernel<<<CN/256, 256>>>(frac, lengths, angles);
    vec_kernel<<<CE/256, 256>>>(edge_index);
    rbf_kernel<<<(CE*CNR)/256, 256>>>();
    cbf_kernel<<<CT/256, 256>>>(id3_ji, id3_kj);
    h0_kernel<<<CN, 128>>>(atom_emb, W_hz, noise, atom_types);

    dim3 gEE(CEE/64, CE/128);   // E x 128
    dim3 gED(CDT/64, CE/128);   // E x 64
    dim3 gNN(CEE/64, CN/128);   // N x 128

    // ---- m init: split W_edge into W1(h_src) | W2(h_dst) | W3(rbf) ----
    gemm_tf32<0><<<gNN, 128>>>(p_h, W_edge,            nullptr, p_hs, CN, CEE, CEA);
    gemm_tf32<0><<<gNN, 128>>>(p_h, W_edge + 128*CEE,  nullptr, p_ht, CN, CEE, CEA);
    gemm_tf32<0><<<gEE, 128>>>(p_rbf, W_edge + 256*CEE, nullptr, p_R, CE, CEE, CNR);
    minit_kernel<<<(CE*CEE)/256, 256>>>(edge_index);

    for (int b = 0; b < 3; b++) {
        const float* Wm_b    = Wm    + b*CEE*CEE;
        const float* Wr1_b   = Wr1   + b*CNR*CEE;
        const float* Wdown_b = Wdown + b*CEE*CDT;
        const float* Wcbf_b  = Wcbf  + b*CNS*CDT;
        const float* Wup_b   = Wup   + b*CDT*CEE;
        const float* Wa_b    = Wa    + b*CEE*CEA;
        const float* Wr2_b   = Wr2   + b*CNR*CEA;
        const float* Wh_b    = Wh    + b*CEA*CEA;
        const float* Ws_b    = Ws    + b*CEA*CEE;
        const float* Wt_b    = Wt    + b*CEA*CEE;

        // x = (silu(m@Wm) * (rbf@Wr1)) @ Wdown
        gemm_tf32<0><<<gEE, 128>>>(p_rbf, Wr1_b, nullptr, p_R, CE, CEE, CNR);
        gemm_tf32<1><<<gEE, 128>>>(p_m,   Wm_b,  p_R,     p_P, CE, CEE, CEE);
        gemm_tf32<0><<<gED, 128>>>(p_P,   Wdown_b, nullptr, p_X, CE, CDT, CEE);

        // t = x[id3_kj] * (cbf@Wcbf); S = seg(t, id3_ji); m += silu(S@Wup)
        zero_k<<<(CE*CDT)/256, 256>>>(p_S, CE*CDT);
        triplet_kernel<<<CT/4, 256>>>(Wcbf_b, id3_ji, id3_kj);
        gemm_tf32<2><<<gEE, 128>>>(p_S, Wup_b, nullptr, p_m, CE, CEE, CDT);

        // a = seg(silu(m@Wa) * (rbf@Wr2), dst); h += silu(a@Wh)
        gemm_tf32<0><<<gEE, 128>>>(p_rbf, Wr2_b, nullptr, p_R, CE, CEA, CNR);
        gemm_tf32<1><<<gEE, 128>>>(p_m,   Wa_b,  p_R,     p_P, CE, CEA, CEE);
        zero_k<<<(CN*CEA)/256, 256>>>(p_a, CN*CEA);
        scatter_a_kernel<<<(CE*CEA)/256, 256>>>(edge_index);
        gemm_tf32<2><<<gNN, 128>>>(p_a, Wh_b, nullptr, p_h, CN, CEA, CEA);

        // m += silu(h[src]@Ws + h[dst]@Wt)
        gemm_tf32<0><<<gNN, 128>>>(p_h, Ws_b, nullptr, p_hs, CN, CEE, CEA);
        gemm_tf32<0><<<gNN, 128>>>(p_h, Wt_b, nullptr, p_ht, CN, CEE, CEA);
        mupd_kernel<<<(CE*CEE)/256, 256>>>(edge_index);
    }

    // ---- readout ----
    gemm_tf32<0><<<dim3(CLAT/64, CN/128), 128>>>(p_h, W_out, nullptr, p_hs, CN, CLAT, CEA);
    z_kernel<<<CB, CLAT>>>();
    fc0_kernel<<<CB, CHID>>>(W_fc0, b_fc0);
    fc1_kernel<<<CB, CHID>>>(W_fc1, b_fc1);
    fc2_kernel<<<CB, CHID>>>(W_fc2, b_fc2, (float*)d_out);
}

// round 9
// speedup vs baseline: 1.0020x; 1.0001x over previous
#include <cuda_runtime.h>
#include <math.h>
#include <stdint.h>

// ---- problem constants ----
#define CB   128
#define CNA  32
#define CN   4096      // atoms
#define CE   65536     // edges
#define CT   262144    // triplets
#define CNR  64
#define CNS  16
#define CEA  128
#define CEE  128
#define CDT  64
#define CLAT 128
#define CHID 256
#define CNC  230

// ---- scratch (device globals: no allocation allowed) ----
__device__ float g_pos[CN*3];
__device__ float g_vec[CE*3];
__device__ float g_rbf[CE*CNR];
__device__ float g_cbf[CT*CNS];
__device__ float g_h [CN*CEA];
__device__ float g_hs[CN*CEA];
__device__ float g_ht[CN*CEA];
__device__ float g_a [CN*CEA];
__device__ float g_m [CE*CEE];
__device__ float g_P [CE*CEE];
__device__ float g_R [CE*CEE];
__device__ float g_X [CE*CDT];
__device__ float g_S [CE*CDT];
__device__ float g_z [CB*CLAT];
__device__ float g_x1[CB*CHID];
__device__ float g_x2[CB*CHID];

__device__ __forceinline__ float siluf(float x) { return x / (1.0f + expf(-x)); }

__device__ __forceinline__ uint32_t f2tf32(float x) {
    uint32_t r;
    asm("cvt.rna.tf32.f32 %0, %1;" : "=r"(r) : "f"(x));
    return r;
}

__device__ __forceinline__ void mma_tf32(float c[4], const uint32_t a[4], const uint32_t b[2]) {
    asm volatile(
        "mma.sync.aligned.m16n8k8.row.col.f32.tf32.tf32.f32 "
        "{%0,%1,%2,%3}, {%4,%5,%6,%7}, {%8,%9}, {%0,%1,%2,%3};"
        : "+f"(c[0]), "+f"(c[1]), "+f"(c[2]), "+f"(c[3])
        : "r"(a[0]), "r"(a[1]), "r"(a[2]), "r"(a[3]), "r"(b[0]), "r"(b[1]));
}

// ============================================================
// TF32 tensor-core GEMM: C[M,N] = epi(A[M,K] @ Bw[K,N])
// CTA tile 128x64, 4 warps (2x2), warp tile 64x32, BK=16,
// double-buffered smem, XOR-swizzled A tile.
// Requires: M%128==0, N%64==0, K%16==0 (true for all calls here).
// EPI 0: C = acc
// EPI 1: C = silu(acc) * D
// EPI 2: C += silu(acc)
// ============================================================
template<int EPI>
__global__ void __launch_bounds__(128)
gemm_tf32(const float* __restrict__ A, const float* __restrict__ Bw,
          const float* __restrict__ D, float* __restrict__ C,
          int M, int N, int K)
{
    __shared__ uint32_t As[2][16][136];  // [buf][k][m swizzled], stride 136 -> bank = 8k+m
    __shared__ uint32_t Bs[2][16][72];   // [buf][k][n], stride 72 -> bank = 8k+n

    const int tid  = threadIdx.x;
    const int lane = tid & 31;
    const int wid  = tid >> 5;
    const int wm   = (wid & 1) * 64;
    const int wn   = (wid >> 1) * 32;
    const int m0   = blockIdx.y * 128;
    const int n0   = blockIdx.x * 64;
    const int nk   = K >> 4;

    // A-load geometry: thread owns row (tid>>2)+32q, float4 at f4*4 within BK
    const int arow = tid >> 2;
    const int af4  = tid & 3;
    // B-load geometry: thread owns k=(tid>>4)+8r, 4 floats at (tid&15)*4
    const int bk   = tid >> 4;
    const int bn4  = (tid & 15) << 2;

    float4 areg[4];
    float4 breg[2];

    auto gload = [&](int k0) {
        #pragma unroll
        for (int q = 0; q < 4; q++) {
            int m = q * 32 + arow;
            areg[q] = *reinterpret_cast<const float4*>(A + (size_t)(m0 + m) * K + k0 + af4 * 4);
        }
        #pragma unroll
        for (int r = 0; r < 2; r++) {
            int k = bk + r * 8;
            breg[r] = *reinterpret_cast<const float4*>(Bw + (size_t)(k0 + k) * N + n0 + bn4);
        }
    };

    auto ssave = [&](int buf) {
        // A: k rows af4*4..af4*4+3, logical col m, physical col m ^ (af4<<3)
        #pragma unroll
        for (int q = 0; q < 4; q++) {
            int m  = q * 32 + arow;
            int mc = m ^ (af4 << 3);
            As[buf][af4 * 4 + 0][mc] = f2tf32(areg[q].x);
            As[buf][af4 * 4 + 1][mc] = f2tf32(areg[q].y);
            As[buf][af4 * 4 + 2][mc] = f2tf32(areg[q].z);
            As[buf][af4 * 4 + 3][mc] = f2tf32(areg[q].w);
        }
        #pragma unroll
        for (int r = 0; r < 2; r++) {
            int k = bk + r * 8;
            uint4 v;
            v.x = f2tf32(breg[r].x); v.y = f2tf32(breg[r].y);
            v.z = f2tf32(breg[r].z); v.w = f2tf32(breg[r].w);
            *reinterpret_cast<uint4*>(&Bs[buf][k][bn4]) = v;
        }
    };

    float acc[4][4][4] = {};

    gload(0);
    ssave(0);
    __syncthreads();

    for (int kb = 0; kb < nk; kb++) {
        int cur = kb & 1;
        if (kb + 1 < nk) gload((kb + 1) << 4);

        #pragma unroll
        for (int kt = 0; kt < 2; kt++) {
            uint32_t af[4][4], bf[4][2];
            int kr  = kt * 8 + (lane & 3);
            int sw0 = ((kr >> 2) & 3) << 3;
            int sw1 = (((kr + 4) >> 2) & 3) << 3;
            #pragma unroll
            for (int mt = 0; mt < 4; mt++) {
                int m = wm + mt * 16 + (lane >> 2);
                af[mt][0] = As[cur][kr    ][m       ^ sw0];
                af[mt][1] = As[cur][kr    ][(m + 8) ^ sw0];
                af[mt][2] = As[cur][kr + 4][m       ^ sw1];
                af[mt][3] = As[cur][kr + 4][(m + 8) ^ sw1];
            }
            #pragma unroll
            for (int nt = 0; nt < 4; nt++) {
                int n = wn + nt * 8 + (lane >> 2);
                bf[nt][0] = Bs[cur][kr    ][n];
                bf[nt][1] = Bs[cur][kr + 4][n];
            }
            #pragma unroll
            for (int mt = 0; mt < 4; mt++)
                #pragma unroll
                for (int nt = 0; nt < 4; nt++)
                    mma_tf32(acc[mt][nt], af[mt], bf[nt]);
        }

        if (kb + 1 < nk) ssave(cur ^ 1);
        __syncthreads();
    }

    // Epilogue
    #pragma unroll
    for (int mt = 0; mt < 4; mt++) {
        #pragma unroll
        for (int nt = 0; nt < 4; nt++) {
            int row = m0 + wm + mt * 16 + (lane >> 2);
            int col = n0 + wn + nt * 8 + ((lane & 3) << 1);
            size_t i0 = (size_t)row * N + col;
            size_t i1 = (size_t)(row + 8) * N + col;
            float2 v0 = make_float2(acc[mt][nt][0], acc[mt][nt][1]);
            float2 v1 = make_float2(acc[mt][nt][2], acc[mt][nt][3]);
            if (EPI == 0) {
                *reinterpret_cast<float2*>(C + i0) = v0;
                *reinterpret_cast<float2*>(C + i1) = v1;
            } else if (EPI == 1) {
                float2 d0 = *reinterpret_cast<const float2*>(D + i0);
                float2 d1 = *reinterpret_cast<const float2*>(D + i1);
                v0.x = siluf(v0.x) * d0.x; v0.y = siluf(v0.y) * d0.y;
                v1.x = siluf(v1.x) * d1.x; v1.y = siluf(v1.y) * d1.y;
                *reinterpret_cast<float2*>(C + i0) = v0;
                *reinterpret_cast<float2*>(C + i1) = v1;
            } else {
                float2 c0 = *reinterpret_cast<const float2*>(C + i0);
                float2 c1 = *reinterpret_cast<const float2*>(C + i1);
                c0.x += siluf(v0.x); c0.y += siluf(v0.y);
                c1.x += siluf(v1.x); c1.y += siluf(v1.y);
                *reinterpret_cast<float2*>(C + i0) = c0;
                *reinterpret_cast<float2*>(C + i1) = c1;
            }
        }
    }
}

__global__ void zero_k(float* __restrict__ p, int n)
{
    int i = blockIdx.x * blockDim.x + threadIdx.x;
    if (i < n) p[i] = 0.0f;
}

// ---- geometry ----
__global__ void pos_kernel(const float* __restrict__ frac, const float* __restrict__ len,
                           const float* __restrict__ ang)
{
    int n = blockIdx.x * blockDim.x + threadIdx.x;
    if (n >= CN) return;
    int b = n >> 5;
    const float D2R = 0.017453292519943295f;
    float La = len[b*3+0], Lb = len[b*3+1], Lc = len[b*3+2];
    float al = ang[b*3+0]*D2R, be = ang[b*3+1]*D2R, ga = ang[b*3+2]*D2R;
    float ca = cosf(al), cb = cosf(be), cg = cosf(ga), sg = sinf(ga);
    float v1x = La;
    float v2x = Lb * cg, v2y = Lb * sg;
    float cx = cb;
    float cy = (ca - cb * cg) / sg;
    float cz = sqrtf(fmaxf(1.0f - cx*cx - cy*cy, 1e-8f));
    float v3x = Lc * cx, v3y = Lc * cy, v3z = Lc * cz;
    float f0 = frac[n*3+0], f1 = frac[n*3+1], f2 = frac[n*3+2];
    g_pos[n*3+0] = f0*v1x + f1*v2x + f2*v3x;
    g_pos[n*3+1] = f1*v2y + f2*v3y;
    g_pos[n*3+2] = f2*v3z;
}

__global__ void vec_kernel(const int* __restrict__ ei)
{
    int e = blockIdx.x * blockDim.x + threadIdx.x;
    if (e >= CE) return;
    int s = ei[e], d = ei[CE + e];
    g_vec[e*3+0] = g_pos[d*3+0] - g_pos[s*3+0];
    g_vec[e*3+1] = g_pos[d*3+1] - g_pos[s*3+1];
    g_vec[e*3+2] = g_pos[d*3+2] - g_pos[s*3+2];
}

__global__ void rbf_kernel()
{
    int idx = blockIdx.x * blockDim.x + threadIdx.x;  // < CE*64
    int e = idx >> 6, r = idx & 63;
    float vx = g_vec[e*3+0], vy = g_vec[e*3+1], vz = g_vec[e*3+2];
    float d = sqrtf(vx*vx + vy*vy + vz*vz + 1e-12f);
    float ds = d * (1.0f / 7.0f);
    float env = 0.0f;
    if (ds < 1.0f) {
        float ds2 = ds*ds, ds4 = ds2*ds2, ds5 = ds4*ds;
        float ds6 = ds5*ds, ds7 = ds6*ds;
        env = 1.0f - 21.0f*ds5 + 35.0f*ds6 - 15.0f*ds7;
    }
    float nn = (float)(r + 1);
    g_rbf[idx] = env * 0.5345224838248488f * sinf(nn * 3.14159265358979323846f * ds) / d;
}

__global__ void cbf_kernel(const int* __restrict__ ji, const int* __restrict__ kj)
{
    int t = blockIdx.x * blockDim.x + threadIdx.x;
    if (t >= CT) return;
    int a = ji[t], b2 = kj[t];
    float ax = g_vec[a*3+0], ay = g_vec[a*3+1], az = g_vec[a*3+2];
    float bx = g_vec[b2*3+0], by = g_vec[b2*3+1], bz = g_vec[b2*3+2];
    float dot = ax*bx + ay*by + az*bz;
    float n1 = sqrtf(ax*ax + ay*ay + az*az);
    float n2 = sqrtf(bx*bx + by*by + bz*bz);
    float c = dot / (n1 * n2 + 1e-9f);
    c = fminf(fmaxf(c, -0.999999f), 0.999999f);
    float angv = acosf(c);
    #pragma unroll
    for (int s = 0; s < CNS; s++) g_cbf[t*CNS + s] = cosf((float)s * angv);
}

// h = silu(concat(atom_emb[atype], noise) @ W_hz), K = 129
__global__ void h0_kernel(const float* __restrict__ atom_emb, const float* __restrict__ W_hz,
                          const float* __restrict__ noise, const int* __restrict__ atype)
{
    __shared__ float emb[128];
    int n = blockIdx.x, j = threadIdx.x;
    emb[j] = atom_emb[atype[n] * 128 + j];
    __syncthreads();
    float acc = noise[n >> 5] * W_hz[128 * 128 + j];
    #pragma unroll 8
    for (int k = 0; k < 128; k++) acc = fmaf(emb[k], W_hz[k * 128 + j], acc);
    g_h[n * 128 + j] = siluf(acc);
}

// m = silu(Hs0[src] + Hd0[dst] + G)   (G staged in g_R)
__global__ void minit_kernel(const int* __restrict__ ei)
{
    int idx = blockIdx.x * blockDim.x + threadIdx.x;  // < CE*128
    int e = idx >> 7, j = idx & 127;
    int s = ei[e], d = ei[CE + e];
    g_m[idx] = siluf(g_hs[s*128 + j] + g_ht[d*128 + j] + g_R[idx]);
}

// m += silu(hs[src] + ht[dst])
__global__ void mupd_kernel(const int* __restrict__ ei)
{
    int idx = blockIdx.x * blockDim.x + threadIdx.x;
    int e = idx >> 7, j = idx & 127;
    int s = ei[e], d = ei[CE + e];
    g_m[idx] += siluf(g_hs[s*128 + j] + g_ht[d*128 + j]);
}

// t = X[id3_kj] * (cbf @ Wcbf[b]); scatter-add into S by id3_ji.
// One block = 4 triplets x 64 outputs.
__global__ void triplet_kernel(const float* __restrict__ Wc,
                               const int* __restrict__ ji, const int* __restrict__ kj)
{
    __shared__ float ws[CNS * 64];   // 1024
    __shared__ float cs[4 * CNS];    // 64
    int tid = threadIdx.x;
    #pragma unroll
    for (int i = 0; i < 4; i++) ws[tid + 256 * i] = Wc[tid + 256 * i];
    int t0 = blockIdx.x << 2;
    if (tid < 64) cs[tid] = g_cbf[(t0 << 4) + tid];
    __syncthreads();
    int lt = tid >> 6, d = tid & 63;
    int t = t0 + lt;
    float acc = 0.0f;
    #pragma unroll
    for (int s = 0; s < CNS; s++)
        acc = fmaf(cs[(lt << 4) + s], ws[(s << 6) + d], acc);
    float val = acc * g_X[kj[t] * 64 + d];
    atomicAdd(&g_S[ji[t] * 64 + d], val);
}

// a[dst] += P  (segment sum by dst)
__global__ void scatter_a_kernel(const int* __restrict__ ei)
{
    int idx = blockIdx.x * blockDim.x + threadIdx.x;  // < CE*128
    int e = idx >> 7, j = idx & 127;
    atomicAdd(&g_a[ei[CE + e] * 128 + j], g_P[idx]);
}

// z = batch-mean of hW (staged in g_hs)
__global__ void z_kernel()
{
    int b = blockIdx.x, j = threadIdx.x;
    float s = 0.0f;
    #pragma unroll
    for (int i = 0; i < CNA; i++) s += g_hs[(b * CNA + i) * 128 + j];
    g_z[b * 128 + j] = s * (1.0f / (float)CNA);
}

__global__ void fc0_kernel(const float* __restrict__ W, const float* __restrict__ bias)
{
    __shared__ float zr[CLAT];
    int b = blockIdx.x, j = threadIdx.x;
    if (j < CLAT) zr[j] = g_z[b * CLAT + j];
    __syncthreads();
    float acc = bias[j];
    #pragma unroll 8
    for (int k = 0; k < CLAT; k++) acc = fmaf(zr[k], W[k * CHID + j], acc);
    g_x1[b * CHID + j] = fmaxf(acc, 0.0f);
}

__global__ void fc1_kernel(const float* __restrict__ W, const float* __restrict__ bias)
{
    __shared__ float xr[CHID];
    int b = blockIdx.x, j = threadIdx.x;
    xr[j] = g_x1[b * CHID + j];
    __syncthreads();
    float acc = bias[j];
    #pragma unroll 8
    for (int k = 0; k < CHID; k++) acc = fmaf(xr[k], W[k * CHID + j], acc);
    g_x2[b * CHID + j] = fmaxf(acc, 0.0f);
}

__global__ void fc2_kernel(const float* __restrict__ W, const float* __restrict__ bias,
                           float* __restrict__ out)
{
    __shared__ float xr[CHID];
    int b = blockIdx.x, j = threadIdx.x;
    xr[j] = g_x2[b * CHID + j];
    __syncthreads();
    if (j >= CNC) return;
    float acc = bias[j];
    #pragma unroll 8
    for (int k = 0; k < CHID; k++) acc = fmaf(xr[k], W[k * CNC + j], acc);
    out[b * CNC + j] = acc;
}

// ============================================================
extern "C" void kernel_launch(void* const* d_in, const int* in_sizes, int n_in,
                              void* d_out, int out_size)
{
    const float *noise, *frac, *lengths, *angles, *atom_emb, *W_hz, *W_edge;
    const float *Wm, *Wr1, *Wdown, *Wcbf, *Wup, *Wa, *Wr2, *Wh, *Ws, *Wt;
    const float *W_out, *W_fc0, *b_fc0, *W_fc1, *b_fc1, *W_fc2, *b_fc2;
    const int *atom_types, *edge_index, *id3_ji, *id3_kj;

    noise   = (const float*)d_in[0];
    frac    = (const float*)d_in[1];
    lengths = (const float*)d_in[2];
    angles  = (const float*)d_in[3];
    if (in_sizes[4] == CN) {
        // setup_inputs dict order
        atom_types = (const int*)d_in[4];
        edge_index = (const int*)d_in[6];
        id3_ji     = (const int*)d_in[7];
        id3_kj     = (const int*)d_in[8];
        atom_emb = (const float*)d_in[9];  W_hz  = (const float*)d_in[10];
        W_edge  = (const float*)d_in[11];  Wm    = (const float*)d_in[12];
        Wr1     = (const float*)d_in[13];  Wdown = (const float*)d_in[14];
        Wcbf    = (const float*)d_in[15];  Wup   = (const float*)d_in[16];
        Wa      = (const float*)d_in[17];  Wr2   = (const float*)d_in[18];
        Wh      = (const float*)d_in[19];  Ws    = (const float*)d_in[20];
        Wt      = (const float*)d_in[21];  W_out = (const float*)d_in[22];
        W_fc0   = (const float*)d_in[23];  b_fc0 = (const float*)d_in[24];
        W_fc1   = (const float*)d_in[25];  b_fc1 = (const float*)d_in[26];
        W_fc2   = (const float*)d_in[27];  b_fc2 = (const float*)d_in[28];
    } else {
        // reference() signature order
        atom_emb = (const float*)d_in[4];  W_hz  = (const float*)d_in[5];
        W_edge  = (const float*)d_in[6];   Wm    = (const float*)d_in[7];
        Wr1     = (const float*)d_in[8];   Wdown = (const float*)d_in[9];
        Wcbf    = (const float*)d_in[10];  Wup   = (const float*)d_in[11];
        Wa      = (const float*)d_in[12];  Wr2   = (const float*)d_in[13];
        Wh      = (const float*)d_in[14];  Ws    = (const float*)d_in[15];
        Wt      = (const float*)d_in[16];  W_out = (const float*)d_in[17];
        W_fc0   = (const float*)d_in[18];  b_fc0 = (const float*)d_in[19];
        W_fc1   = (const float*)d_in[20];  b_fc1 = (const float*)d_in[21];
        W_fc2   = (const float*)d_in[22];  b_fc2 = (const float*)d_in[23];
        atom_types = (const int*)d_in[24];
        edge_index = (const int*)d_in[26];
        id3_ji     = (const int*)d_in[27];
        id3_kj     = (const int*)d_in[28];
    }

    float *p_h, *p_hs, *p_ht, *p_a, *p_m, *p_P, *p_R, *p_X, *p_S, *p_rbf;
    cudaGetSymbolAddress((void**)&p_h,  g_h);
    cudaGetSymbolAddress((void**)&p_hs, g_hs);
    cudaGetSymbolAddress((void**)&p_ht, g_ht);
    cudaGetSymbolAddress((void**)&p_a,  g_a);
    cudaGetSymbolAddress((void**)&p_m,  g_m);
    cudaGetSymbolAddress((void**)&p_P,  g_P);
    cudaGetSymbolAddress((void**)&p_R,  g_R);
    cudaGetSymbolAddress((void**)&p_X,  g_X);
    cudaGetSymbolAddress((void**)&p_S,  g_S);
    cudaGetSymbolAddress((void**)&p_rbf, g_rbf);

    // ---- geometry / features ----
    pos_kernel<<<CN/256, 256>>>(frac, lengths, angles);
    vec_kernel<<<CE/256, 256>>>(edge_index);
    rbf_kernel<<<(CE*CNR)/256, 256>>>();
    cbf_kernel<<<CT/256, 256>>>(id3_ji, id3_kj);
    h0_kernel<<<CN, 128>>>(atom_emb, W_hz, noise, atom_types);

    dim3 gEE(CEE/64, CE/128);   // E x 128
    dim3 gED(CDT/64, CE/128);   // E x 64
    dim3 gNN(CEE/64, CN/128);   // N x 128

    // ---- m init: split W_edge into W1(h_src) | W2(h_dst) | W3(rbf) ----
    gemm_tf32<0><<<gNN, 128>>>(p_h, W_edge,            nullptr, p_hs, CN, CEE, CEA);
    gemm_tf32<0><<<gNN, 128>>>(p_h, W_edge + 128*CEE,  nullptr, p_ht, CN, CEE, CEA);
    gemm_tf32<0><<<gEE, 128>>>(p_rbf, W_edge + 256*CEE, nullptr, p_R, CE, CEE, CNR);
    minit_kernel<<<(CE*CEE)/256, 256>>>(edge_index);

    for (int b = 0; b < 3; b++) {
        const float* Wm_b    = Wm    + b*CEE*CEE;
        const float* Wr1_b   = Wr1   + b*CNR*CEE;
        const float* Wdown_b = Wdown + b*CEE*CDT;
        const float* Wcbf_b  = Wcbf  + b*CNS*CDT;
        const float* Wup_b   = Wup   + b*CDT*CEE;
        const float* Wa_b    = Wa    + b*CEE*CEA;
        const float* Wr2_b   = Wr2   + b*CNR*CEA;
        const float* Wh_b    = Wh    + b*CEA*CEA;
        const float* Ws_b    = Ws    + b*CEA*CEE;
        const float* Wt_b    = Wt    + b*CEA*CEE;

        // x = (silu(m@Wm) * (rbf@Wr1)) @ Wdown
        gemm_tf32<0><<<gEE, 128>>>(p_rbf, Wr1_b, nullptr, p_R, CE, CEE, CNR);
        gemm_tf32<1><<<gEE, 128>>>(p_m,   Wm_b,  p_R,     p_P, CE, CEE, CEE);
        gemm_tf32<0><<<gED, 128>>>(p_P,   Wdown_b, nullptr, p_X, CE, CDT, CEE);

        // t = x[id3_kj] * (cbf@Wcbf); S = seg(t, id3_ji); m += silu(S@Wup)
        zero_k<<<(CE*CDT)/256, 256>>>(p_S, CE*CDT);
        triplet_kernel<<<CT/4, 256>>>(Wcbf_b, id3_ji, id3_kj);
        gemm_tf32<2><<<gEE, 128>>>(p_S, Wup_b, nullptr, p_m, CE, CEE, CDT);

        // a = seg(silu(m@Wa) * (rbf@Wr2), dst); h += silu(a@Wh)
        gemm_tf32<0><<<gEE, 128>>>(p_rbf, Wr2_b, nullptr, p_R, CE, CEA, CNR);
        gemm_tf32<1><<<gEE, 128>>>(p_m,   Wa_b,  p_R,     p_P, CE, CEA, CEE);
        zero_k<<<(CN*CEA)/256, 256>>>(p_a, CN*CEA);
        scatter_a_kernel<<<(CE*CEA)/256, 256>>>(edge_index);
        gemm_tf32<2><<<gNN, 128>>>(p_a, Wh_b, nullptr, p_h, CN, CEA, CEA);

        // m += silu(h[src]@Ws + h[dst]@Wt)
        gemm_tf32<0><<<gNN, 128>>>(p_h, Ws_b, nullptr, p_hs, CN, CEE, CEA);
        gemm_tf32<0><<<gNN, 128>>>(p_h, Wt_b, nullptr, p_ht, CN, CEE, CEA);
        mupd_kernel<<<(CE*CEE)/256, 256>>>(edge_index);
    }

    // ---- readout ----
    gemm_tf32<0><<<dim3(CLAT/64, CN/128), 128>>>(p_h, W_out, nullptr, p_hs, CN, CLAT, CEA);
    z_kernel<<<CB, CLAT>>>();
    fc0_kernel<<<CB, CHID>>>(W_fc0, b_fc0);
    fc1_kernel<<<CB, CHID>>>(W_fc1, b_fc1);
    fc2_kernel<<<CB, CHID>>>(W_fc2, b_fc2, (float*)d_out);
}

// round 13
// speedup vs baseline: 1.0020x; 1.0001x over previous
#include <cuda_runtime.h>
#include <math.h>
#include <stdint.h>

// ---- problem constants ----
#define CB   128
#define CNA  32
#define CN   4096      // atoms
#define CE   65536     // edges
#define CT   262144    // triplets
#define CNR  64
#define CNS  16
#define CEA  128
#define CEE  128
#define CDT  64
#define CLAT 128
#define CHID 256
#define CNC  230

// ---- scratch (device globals: no allocation allowed) ----
__device__ float g_pos[CN*3];
__device__ float g_vec[CE*3];
__device__ float g_rbf[CE*CNR];
__device__ float g_cbf[CT*CNS];
__device__ float g_h [CN*CEA];
__device__ float g_hs[CN*CEA];
__device__ float g_ht[CN*CEA];
__device__ float g_a [CN*CEA];
__device__ float g_m [CE*CEE];
__device__ float g_P [CE*CEE];
__device__ float g_R [CE*CEE];
__device__ float g_X [CE*CDT];
__device__ float g_S [CE*CDT];
__device__ float g_z [CB*CLAT];
__device__ float g_x1[CB*CHID];
__device__ float g_x2[CB*CHID];

__device__ __forceinline__ float siluf(float x) { return x / (1.0f + expf(-x)); }

__device__ __forceinline__ uint32_t f2tf32(float x) {
    uint32_t r;
    asm("cvt.rna.tf32.f32 %0, %1;" : "=r"(r) : "f"(x));
    return r;
}

__device__ __forceinline__ void mma_tf32(float c[4], const uint32_t a[4], const uint32_t b[2]) {
    asm volatile(
        "mma.sync.aligned.m16n8k8.row.col.f32.tf32.tf32.f32 "
        "{%0,%1,%2,%3}, {%4,%5,%6,%7}, {%8,%9}, {%0,%1,%2,%3};"
        : "+f"(c[0]), "+f"(c[1]), "+f"(c[2]), "+f"(c[3])
        : "r"(a[0]), "r"(a[1]), "r"(a[2]), "r"(a[3]), "r"(b[0]), "r"(b[1]));
}

// ============================================================
// TF32 tensor-core GEMM: C[M,N] = epi(A[M,K] @ Bw[K,N])
// CTA tile 128x64, 4 warps (2x2), warp tile 64x32, BK=16,
// double-buffered smem, XOR-swizzled A tile.
// Requires: M%128==0, N%64==0, K%16==0 (true for all calls here).
// EPI 0: C = acc
// EPI 1: C = silu(acc) * D
// EPI 2: C += silu(acc)
// ============================================================
template<int EPI>
__global__ void __launch_bounds__(128)
gemm_tf32(const float* __restrict__ A, const float* __restrict__ Bw,
          const float* __restrict__ D, float* __restrict__ C,
          int M, int N, int K)
{
    __shared__ uint32_t As[2][16][136];  // [buf][k][m swizzled], stride 136 -> bank = 8k+m
    __shared__ uint32_t Bs[2][16][72];   // [buf][k][n], stride 72 -> bank = 8k+n

    const int tid  = threadIdx.x;
    const int lane = tid & 31;
    const int wid  = tid >> 5;
    const int wm   = (wid & 1) * 64;
    const int wn   = (wid >> 1) * 32;
    const int m0   = blockIdx.y * 128;
    const int n0   = blockIdx.x * 64;
    const int nk   = K >> 4;

    // A-load geometry: thread owns row (tid>>2)+32q, float4 at f4*4 within BK
    const int arow = tid >> 2;
    const int af4  = tid & 3;
    // B-load geometry: thread owns k=(tid>>4)+8r, 4 floats at (tid&15)*4
    const int bk   = tid >> 4;
    const int bn4  = (tid & 15) << 2;

    float4 areg[4];
    float4 breg[2];

    auto gload = [&](int k0) {
        #pragma unroll
        for (int q = 0; q < 4; q++) {
            int m = q * 32 + arow;
            areg[q] = *reinterpret_cast<const float4*>(A + (size_t)(m0 + m) * K + k0 + af4 * 4);
        }
        #pragma unroll
        for (int r = 0; r < 2; r++) {
            int k = bk + r * 8;
            breg[r] = *reinterpret_cast<const float4*>(Bw + (size_t)(k0 + k) * N + n0 + bn4);
        }
    };

    auto ssave = [&](int buf) {
        // A: k rows af4*4..af4*4+3, logical col m, physical col m ^ (af4<<3)
        #pragma unroll
        for (int q = 0; q < 4; q++) {
            int m  = q * 32 + arow;
            int mc = m ^ (af4 << 3);
            As[buf][af4 * 4 + 0][mc] = f2tf32(areg[q].x);
            As[buf][af4 * 4 + 1][mc] = f2tf32(areg[q].y);
            As[buf][af4 * 4 + 2][mc] = f2tf32(areg[q].z);
            As[buf][af4 * 4 + 3][mc] = f2tf32(areg[q].w);
        }
        #pragma unroll
        for (int r = 0; r < 2; r++) {
            int k = bk + r * 8;
            uint4 v;
            v.x = f2tf32(breg[r].x); v.y = f2tf32(breg[r].y);
            v.z = f2tf32(breg[r].z); v.w = f2tf32(breg[r].w);
            *reinterpret_cast<uint4*>(&Bs[buf][k][bn4]) = v;
        }
    };

    float acc[4][4][4] = {};

    gload(0);
    ssave(0);
    __syncthreads();

    for (int kb = 0; kb < nk; kb++) {
        int cur = kb & 1;
        if (kb + 1 < nk) gload((kb + 1) << 4);

        #pragma unroll
        for (int kt = 0; kt < 2; kt++) {
            uint32_t af[4][4], bf[4][2];
            int kr  = kt * 8 + (lane & 3);
            int sw0 = ((kr >> 2) & 3) << 3;
            int sw1 = (((kr + 4) >> 2) & 3) << 3;
            #pragma unroll
            for (int mt = 0; mt < 4; mt++) {
                int m = wm + mt * 16 + (lane >> 2);
                af[mt][0] = As[cur][kr    ][m       ^ sw0];
                af[mt][1] = As[cur][kr    ][(m + 8) ^ sw0];
                af[mt][2] = As[cur][kr + 4][m       ^ sw1];
                af[mt][3] = As[cur][kr + 4][(m + 8) ^ sw1];
            }
            #pragma unroll
            for (int nt = 0; nt < 4; nt++) {
                int n = wn + nt * 8 + (lane >> 2);
                bf[nt][0] = Bs[cur][kr    ][n];
                bf[nt][1] = Bs[cur][kr + 4][n];
            }
            #pragma unroll
            for (int mt = 0; mt < 4; mt++)
                #pragma unroll
                for (int nt = 0; nt < 4; nt++)
                    mma_tf32(acc[mt][nt], af[mt], bf[nt]);
        }

        if (kb + 1 < nk) ssave(cur ^ 1);
        __syncthreads();
    }

    // Epilogue
    #pragma unroll
    for (int mt = 0; mt < 4; mt++) {
        #pragma unroll
        for (int nt = 0; nt < 4; nt++) {
            int row = m0 + wm + mt * 16 + (lane >> 2);
            int col = n0 + wn + nt * 8 + ((lane & 3) << 1);
            size_t i0 = (size_t)row * N + col;
            size_t i1 = (size_t)(row + 8) * N + col;
            float2 v0 = make_float2(acc[mt][nt][0], acc[mt][nt][1]);
            float2 v1 = make_float2(acc[mt][nt][2], acc[mt][nt][3]);
            if (EPI == 0) {
                *reinterpret_cast<float2*>(C + i0) = v0;
                *reinterpret_cast<float2*>(C + i1) = v1;
            } else if (EPI == 1) {
                float2 d0 = *reinterpret_cast<const float2*>(D + i0);
                float2 d1 = *reinterpret_cast<const float2*>(D + i1);
                v0.x = siluf(v0.x) * d0.x; v0.y = siluf(v0.y) * d0.y;
                v1.x = siluf(v1.x) * d1.x; v1.y = siluf(v1.y) * d1.y;
                *reinterpret_cast<float2*>(C + i0) = v0;
                *reinterpret_cast<float2*>(C + i1) = v1;
            } else {
                float2 c0 = *reinterpret_cast<const float2*>(C + i0);
                float2 c1 = *reinterpret_cast<const float2*>(C + i1);
                c0.x += siluf(v0.x); c0.y += siluf(v0.y);
                c1.x += siluf(v1.x); c1.y += siluf(v1.y);
                *reinterpret_cast<float2*>(C + i0) = c0;
                *reinterpret_cast<float2*>(C + i1) = c1;
            }
        }
    }
}

__global__ void zero_k(float* __restrict__ p, int n)
{
    int i = blockIdx.x * blockDim.x + threadIdx.x;
    if (i < n) p[i] = 0.0f;
}

// ---- geometry ----
__global__ void pos_kernel(const float* __restrict__ frac, const float* __restrict__ len,
                           const float* __restrict__ ang)
{
    int n = blockIdx.x * blockDim.x + threadIdx.x;
    if (n >= CN) return;
    int b = n >> 5;
    const float D2R = 0.017453292519943295f;
    float La = len[b*3+0], Lb = len[b*3+1], Lc = len[b*3+2];
    float al = ang[b*3+0]*D2R, be = ang[b*3+1]*D2R, ga = ang[b*3+2]*D2R;
    float ca = cosf(al), cb = cosf(be), cg = cosf(ga), sg = sinf(ga);
    float v1x = La;
    float v2x = Lb * cg, v2y = Lb * sg;
    float cx = cb;
    float cy = (ca - cb * cg) / sg;
    float cz = sqrtf(fmaxf(1.0f - cx*cx - cy*cy, 1e-8f));
    float v3x = Lc * cx, v3y = Lc * cy, v3z = Lc * cz;
    float f0 = frac[n*3+0], f1 = frac[n*3+1], f2 = frac[n*3+2];
    g_pos[n*3+0] = f0*v1x + f1*v2x + f2*v3x;
    g_pos[n*3+1] = f1*v2y + f2*v3y;
    g_pos[n*3+2] = f2*v3z;
}

__global__ void vec_kernel(const int* __restrict__ ei)
{
    int e = blockIdx.x * blockDim.x + threadIdx.x;
    if (e >= CE) return;
    int s = ei[e], d = ei[CE + e];
    g_vec[e*3+0] = g_pos[d*3+0] - g_pos[s*3+0];
    g_vec[e*3+1] = g_pos[d*3+1] - g_pos[s*3+1];
    g_vec[e*3+2] = g_pos[d*3+2] - g_pos[s*3+2];
}

__global__ void rbf_kernel()
{
    int idx = blockIdx.x * blockDim.x + threadIdx.x;  // < CE*64
    int e = idx >> 6, r = idx & 63;
    float vx = g_vec[e*3+0], vy = g_vec[e*3+1], vz = g_vec[e*3+2];
    float d = sqrtf(vx*vx + vy*vy + vz*vz + 1e-12f);
    float ds = d * (1.0f / 7.0f);
    float env = 0.0f;
    if (ds < 1.0f) {
        float ds2 = ds*ds, ds4 = ds2*ds2, ds5 = ds4*ds;
        float ds6 = ds5*ds, ds7 = ds6*ds;
        env = 1.0f - 21.0f*ds5 + 35.0f*ds6 - 15.0f*ds7;
    }
    float nn = (float)(r + 1);
    g_rbf[idx] = env * 0.5345224838248488f * sinf(nn * 3.14159265358979323846f * ds) / d;
}

__global__ void cbf_kernel(const int* __restrict__ ji, const int* __restrict__ kj)
{
    int t = blockIdx.x * blockDim.x + threadIdx.x;
    if (t >= CT) return;
    int a = ji[t], b2 = kj[t];
    float ax = g_vec[a*3+0], ay = g_vec[a*3+1], az = g_vec[a*3+2];
    float bx = g_vec[b2*3+0], by = g_vec[b2*3+1], bz = g_vec[b2*3+2];
    float dot = ax*bx + ay*by + az*bz;
    float n1 = sqrtf(ax*ax + ay*ay + az*az);
    float n2 = sqrtf(bx*bx + by*by + bz*bz);
    float c = dot / (n1 * n2 + 1e-9f);
    c = fminf(fmaxf(c, -0.999999f), 0.999999f);
    float angv = acosf(c);
    #pragma unroll
    for (int s = 0; s < CNS; s++) g_cbf[t*CNS + s] = cosf((float)s * angv);
}

// h = silu(concat(atom_emb[atype], noise) @ W_hz), K = 129
__global__ void h0_kernel(const float* __restrict__ atom_emb, const float* __restrict__ W_hz,
                          const float* __restrict__ noise, const int* __restrict__ atype)
{
    __shared__ float emb[128];
    int n = blockIdx.x, j = threadIdx.x;
    emb[j] = atom_emb[atype[n] * 128 + j];
    __syncthreads();
    float acc = noise[n >> 5] * W_hz[128 * 128 + j];
    #pragma unroll 8
    for (int k = 0; k < 128; k++) acc = fmaf(emb[k], W_hz[k * 128 + j], acc);
    g_h[n * 128 + j] = siluf(acc);
}

// m = silu(Hs0[src] + Hd0[dst] + G)   (G staged in g_R)
__global__ void minit_kernel(const int* __restrict__ ei)
{
    int idx = blockIdx.x * blockDim.x + threadIdx.x;  // < CE*128
    int e = idx >> 7, j = idx & 127;
    int s = ei[e], d = ei[CE + e];
    g_m[idx] = siluf(g_hs[s*128 + j] + g_ht[d*128 + j] + g_R[idx]);
}

// m += silu(hs[src] + ht[dst])
__global__ void mupd_kernel(const int* __restrict__ ei)
{
    int idx = blockIdx.x * blockDim.x + threadIdx.x;
    int e = idx >> 7, j = idx & 127;
    int s = ei[e], d = ei[CE + e];
    g_m[idx] += siluf(g_hs[s*128 + j] + g_ht[d*128 + j]);
}

// t = X[id3_kj] * (cbf @ Wcbf[b]); scatter-add into S by id3_ji.
// One block = 4 triplets x 64 outputs.
__global__ void triplet_kernel(const float* __restrict__ Wc,
                               const int* __restrict__ ji, const int* __restrict__ kj)
{
    __shared__ float ws[CNS * 64];   // 1024
    __shared__ float cs[4 * CNS];    // 64
    int tid = threadIdx.x;
    #pragma unroll
    for (int i = 0; i < 4; i++) ws[tid + 256 * i] = Wc[tid + 256 * i];
    int t0 = blockIdx.x << 2;
    if (tid < 64) cs[tid] = g_cbf[(t0 << 4) + tid];
    __syncthreads();
    int lt = tid >> 6, d = tid & 63;
    int t = t0 + lt;
    float acc = 0.0f;
    #pragma unroll
    for (int s = 0; s < CNS; s++)
        acc = fmaf(cs[(lt << 4) + s], ws[(s << 6) + d], acc);
    float val = acc * g_X[kj[t] * 64 + d];
    atomicAdd(&g_S[ji[t] * 64 + d], val);
}

// a[dst] += P  (segment sum by dst)
__global__ void scatter_a_kernel(const int* __restrict__ ei)
{
    int idx = blockIdx.x * blockDim.x + threadIdx.x;  // < CE*128
    int e = idx >> 7, j = idx & 127;
    atomicAdd(&g_a[ei[CE + e] * 128 + j], g_P[idx]);
}

// z = batch-mean of hW (staged in g_hs)
__global__ void z_kernel()
{
    int b = blockIdx.x, j = threadIdx.x;
    float s = 0.0f;
    #pragma unroll
    for (int i = 0; i < CNA; i++) s += g_hs[(b * CNA + i) * 128 + j];
    g_z[b * 128 + j] = s * (1.0f / (float)CNA);
}

__global__ void fc0_kernel(const float* __restrict__ W, const float* __restrict__ bias)
{
    __shared__ float zr[CLAT];
    int b = blockIdx.x, j = threadIdx.x;
    if (j < CLAT) zr[j] = g_z[b * CLAT + j];
    __syncthreads();
    float acc = bias[j];
    #pragma unroll 8
    for (int k = 0; k < CLAT; k++) acc = fmaf(zr[k], W[k * CHID + j], acc);
    g_x1[b * CHID + j] = fmaxf(acc, 0.0f);
}

__global__ void fc1_kernel(const float* __restrict__ W, const float* __restrict__ bias)
{
    __shared__ float xr[CHID];
    int b = blockIdx.x, j = threadIdx.x;
    xr[j] = g_x1[b * CHID + j];
    __syncthreads();
    float acc = bias[j];
    #pragma unroll 8
    for (int k = 0; k < CHID; k++) acc = fmaf(xr[k], W[k * CHID + j], acc);
    g_x2[b * CHID + j] = fmaxf(acc, 0.0f);
}

__global__ void fc2_kernel(const float* __restrict__ W, const float* __restrict__ bias,
                           float* __restrict__ out)
{
    __shared__ float xr[CHID];
    int b = blockIdx.x, j = threadIdx.x;
    xr[j] = g_x2[b * CHID + j];
    __syncthreads();
    if (j >= CNC) return;
    float acc = bias[j];
    #pragma unroll 8
    for (int k = 0; k < CHID; k++) acc = fmaf(xr[k], W[k * CNC + j], acc);
    out[b * CNC + j] = acc;
}

// ============================================================
extern "C" void kernel_launch(void* const* d_in, const int* in_sizes, int n_in,
                              void* d_out, int out_size)
{
    const float *noise, *frac, *lengths, *angles, *atom_emb, *W_hz, *W_edge;
    const float *Wm, *Wr1, *Wdown, *Wcbf, *Wup, *Wa, *Wr2, *Wh, *Ws, *Wt;
    const float *W_out, *W_fc0, *b_fc0, *W_fc1, *b_fc1, *W_fc2, *b_fc2;
    const int *atom_types, *edge_index, *id3_ji, *id3_kj;

    noise   = (const float*)d_in[0];
    frac    = (const float*)d_in[1];
    lengths = (const float*)d_in[2];
    angles  = (const float*)d_in[3];
    if (in_sizes[4] == CN) {
        // setup_inputs dict order
        atom_types = (const int*)d_in[4];
        edge_index = (const int*)d_in[6];
        id3_ji     = (const int*)d_in[7];
        id3_kj     = (const int*)d_in[8];
        atom_emb = (const float*)d_in[9];  W_hz  = (const float*)d_in[10];
        W_edge  = (const float*)d_in[11];  Wm    = (const float*)d_in[12];
        Wr1     = (const float*)d_in[13];  Wdown = (const float*)d_in[14];
        Wcbf    = (const float*)d_in[15];  Wup   = (const float*)d_in[16];
        Wa      = (const float*)d_in[17];  Wr2   = (const float*)d_in[18];
        Wh      = (const float*)d_in[19];  Ws    = (const float*)d_in[20];
        Wt      = (const float*)d_in[21];  W_out = (const float*)d_in[22];
        W_fc0   = (const float*)d_in[23];  b_fc0 = (const float*)d_in[24];
        W_fc1   = (const float*)d_in[25];  b_fc1 = (const float*)d_in[26];
        W_fc2   = (const float*)d_in[27];  b_fc2 = (const float*)d_in[28];
    } else {
        // reference() signature order
        atom_emb = (const float*)d_in[4];  W_hz  = (const float*)d_in[5];
        W_edge  = (const float*)d_in[6];   Wm    = (const float*)d_in[7];
        Wr1     = (const float*)d_in[8];   Wdown = (const float*)d_in[9];
        Wcbf    = (const float*)d_in[10];  Wup   = (const float*)d_in[11];
        Wa      = (const float*)d_in[12];  Wr2   = (const float*)d_in[13];
        Wh      = (const float*)d_in[14];  Ws    = (const float*)d_in[15];
        Wt      = (const float*)d_in[16];  W_out = (const float*)d_in[17];
        W_fc0   = (const float*)d_in[18];  b_fc0 = (const float*)d_in[19];
        W_fc1   = (const float*)d_in[20];  b_fc1 = (const float*)d_in[21];
        W_fc2   = (const float*)d_in[22];  b_fc2 = (const float*)d_in[23];
        atom_types = (const int*)d_in[24];
        edge_index = (const int*)d_in[26];
        id3_ji     = (const int*)d_in[27];
        id3_kj     = (const int*)d_in[28];
    }

    float *p_h, *p_hs, *p_ht, *p_a, *p_m, *p_P, *p_R, *p_X, *p_S, *p_rbf;
    cudaGetSymbolAddress((void**)&p_h,  g_h);
    cudaGetSymbolAddress((void**)&p_hs, g_hs);
    cudaGetSymbolAddress((void**)&p_ht, g_ht);
    cudaGetSymbolAddress((void**)&p_a,  g_a);
    cudaGetSymbolAddress((void**)&p_m,  g_m);
    cudaGetSymbolAddress((void**)&p_P,  g_P);
    cudaGetSymbolAddress((void**)&p_R,  g_R);
    cudaGetSymbolAddress((void**)&p_X,  g_X);
    cudaGetSymbolAddress((void**)&p_S,  g_S);
    cudaGetSymbolAddress((void**)&p_rbf, g_rbf);

    // ---- geometry / features ----
    pos_kernel<<<CN/256, 256>>>(frac, lengths, angles);
    vec_kernel<<<CE/256, 256>>>(edge_index);
    rbf_kernel<<<(CE*CNR)/256, 256>>>();
    cbf_kernel<<<CT/256, 256>>>(id3_ji, id3_kj);
    h0_kernel<<<CN, 128>>>(atom_emb, W_hz, noise, atom_types);

    dim3 gEE(CEE/64, CE/128);   // E x 128
    dim3 gED(CDT/64, CE/128);   // E x 64
    dim3 gNN(CEE/64, CN/128);   // N x 128

    // ---- m init: split W_edge into W1(h_src) | W2(h_dst) | W3(rbf) ----
    gemm_tf32<0><<<gNN, 128>>>(p_h, W_edge,            nullptr, p_hs, CN, CEE, CEA);
    gemm_tf32<0><<<gNN, 128>>>(p_h, W_edge + 128*CEE,  nullptr, p_ht, CN, CEE, CEA);
    gemm_tf32<0><<<gEE, 128>>>(p_rbf, W_edge + 256*CEE, nullptr, p_R, CE, CEE, CNR);
    minit_kernel<<<(CE*CEE)/256, 256>>>(edge_index);

    for (int b = 0; b < 3; b++) {
        const float* Wm_b    = Wm    + b*CEE*CEE;
        const float* Wr1_b   = Wr1   + b*CNR*CEE;
        const float* Wdown_b = Wdown + b*CEE*CDT;
        const float* Wcbf_b  = Wcbf  + b*CNS*CDT;
        const float* Wup_b   = Wup   + b*CDT*CEE;
        const float* Wa_b    = Wa    + b*CEE*CEA;
        const float* Wr2_b   = Wr2   + b*CNR*CEA;
        const float* Wh_b    = Wh    + b*CEA*CEA;
        const float* Ws_b    = Ws    + b*CEA*CEE;
        const float* Wt_b    = Wt    + b*CEA*CEE;

        // x = (silu(m@Wm) * (rbf@Wr1)) @ Wdown
        gemm_tf32<0><<<gEE, 128>>>(p_rbf, Wr1_b, nullptr, p_R, CE, CEE, CNR);
        gemm_tf32<1><<<gEE, 128>>>(p_m,   Wm_b,  p_R,     p_P, CE, CEE, CEE);
        gemm_tf32<0><<<gED, 128>>>(p_P,   Wdown_b, nullptr, p_X, CE, CDT, CEE);

        // t = x[id3_kj] * (cbf@Wcbf); S = seg(t, id3_ji); m += silu(S@Wup)
        zero_k<<<(CE*CDT)/256, 256>>>(p_S, CE*CDT);
        triplet_kernel<<<CT/4, 256>>>(Wcbf_b, id3_ji, id3_kj);
        gemm_tf32<2><<<gEE, 128>>>(p_S, Wup_b, nullptr, p_m, CE, CEE, CDT);

        // a = seg(silu(m@Wa) * (rbf@Wr2), dst); h += silu(a@Wh)
        gemm_tf32<0><<<gEE, 128>>>(p_rbf, Wr2_b, nullptr, p_R, CE, CEA, CNR);
        gemm_tf32<1><<<gEE, 128>>>(p_m,   Wa_b,  p_R,     p_P, CE, CEA, CEE);
        zero_k<<<(CN*CEA)/256, 256>>>(p_a, CN*CEA);
        scatter_a_kernel<<<(CE*CEA)/256, 256>>>(edge_index);
        gemm_tf32<2><<<gNN, 128>>>(p_a, Wh_b, nullptr, p_h, CN, CEA, CEA);

        // m += silu(h[src]@Ws + h[dst]@Wt)
        gemm_tf32<0><<<gNN, 128>>>(p_h, Ws_b, nullptr, p_hs, CN, CEE, CEA);
        gemm_tf32<0><<<gNN, 128>>>(p_h, Wt_b, nullptr, p_ht, CN, CEE, CEA);
        mupd_kernel<<<(CE*CEE)/256, 256>>>(edge_index);
    }

    // ---- readout ----
    gemm_tf32<0><<<dim3(CLAT/64, CN/128), 128>>>(p_h, W_out, nullptr, p_hs, CN, CLAT, CEA);
    z_kernel<<<CB, CLAT>>>();
    fc0_kernel<<<CB, CHID>>>(W_fc0, b_fc0);
    fc1_kernel<<<CB, CHID>>>(W_fc1, b_fc1);
    fc2_kernel<<<CB, CHID>>>(W_fc2, b_fc2, (float*)d_out);
}